// round 14
// baseline (speedup 1.0000x reference)
#include <cuda_runtime.h>
#include <cuda_bf16.h>
#include <cuda_fp16.h>
#include <math.h>
#include <stdint.h>

// Problem constants
#define BATCH 2
#define TSEQ  2048
#define DIM   2048
#define NH    16
#define HD    128
#define MROWS (BATCH * TSEQ)      // 4096
#define KDIM  DIM                 // 2048
#define NELEM ((size_t)BATCH * NH * TSEQ * HD)   // 8.4M

#define RESTORE_SCALE 45.25483399593904f   // sqrt(2048)
#define ATTN_SCALE    11.313708498984761f  // sqrt(128)
#define WSCALE 64.0f
#define INV_WSCALE (1.0f / 64.0f)

// ---------------------------------------------------------------------------
// Scratch (device globals — allocation-free rule)
// ---------------------------------------------------------------------------
// bf16 pairs (high-precision Q/K path)
__device__ __nv_bfloat16 g_xh[(size_t)MROWS * DIM], g_xl[(size_t)MROWS * DIM];
__device__ __nv_bfloat16 g_wqh[(size_t)DIM * DIM], g_wql[(size_t)DIM * DIM];
__device__ __nv_bfloat16 g_wkh[(size_t)DIM * DIM], g_wkl[(size_t)DIM * DIM];
__device__ __nv_bfloat16 g_qh[NELEM], g_ql[NELEM];   // roped+scaled q
__device__ __nv_bfloat16 g_kh[NELEM], g_kl[NELEM];   // roped+scaled k

// fp16 path (V / att / out-proj)
__device__ __half g_xf[(size_t)MROWS * DIM];                 // x fp16 single
__device__ __half g_wvh[(size_t)DIM * DIM], g_wvl[(size_t)DIM * DIM]; // Wv*64
__device__ __half g_woh[(size_t)DIM * DIM], g_wol[(size_t)DIM * DIM]; // Wo*64
__device__ __half g_vh[NELEM], g_vl[NELEM];                  // v fp16 pair
__device__ __half g_af[(size_t)MROWS * DIM];                 // attn out fp16

// RoPE tables: cos/sin for (t, j), t in [0,2048), j in [0,64)
__device__ float g_rc[TSEQ * 64];
__device__ float g_rs[TSEQ * 64];

// ---------------------------------------------------------------------------
// PTX helpers (base sm_103 target safe: ldmatrix / mma.sync / cp.async)
// ---------------------------------------------------------------------------
__device__ __forceinline__ uint32_t smem_u32(const void* p) {
    uint32_t a;
    asm("{ .reg .u64 t; cvta.to.shared.u64 t, %1; cvt.u32.u64 %0, t; }"
        : "=r"(a) : "l"(p));
    return a;
}
__device__ __forceinline__ void ldsm4(uint32_t addr, uint32_t r[4]) {
    asm volatile("ldmatrix.sync.aligned.m8n8.x4.shared.b16 {%0,%1,%2,%3}, [%4];"
        : "=r"(r[0]), "=r"(r[1]), "=r"(r[2]), "=r"(r[3]) : "r"(addr));
}
__device__ __forceinline__ void ldsm4t(uint32_t addr, uint32_t r[4]) {
    asm volatile("ldmatrix.sync.aligned.m8n8.x4.trans.shared.b16 {%0,%1,%2,%3}, [%4];"
        : "=r"(r[0]), "=r"(r[1]), "=r"(r[2]), "=r"(r[3]) : "r"(addr));
}
__device__ __forceinline__ void mma16816(float c[4], const uint32_t a[4],
                                         uint32_t b0, uint32_t b1) {
    asm volatile(
        "mma.sync.aligned.m16n8k16.row.col.f32.bf16.bf16.f32 "
        "{%0,%1,%2,%3}, {%4,%5,%6,%7}, {%8,%9}, {%0,%1,%2,%3};"
        : "+f"(c[0]), "+f"(c[1]), "+f"(c[2]), "+f"(c[3])
        : "r"(a[0]), "r"(a[1]), "r"(a[2]), "r"(a[3]), "r"(b0), "r"(b1));
}
__device__ __forceinline__ void mma16816h(float c[4], const uint32_t a[4],
                                          uint32_t b0, uint32_t b1) {
    asm volatile(
        "mma.sync.aligned.m16n8k16.row.col.f32.f16.f16.f32 "
        "{%0,%1,%2,%3}, {%4,%5,%6,%7}, {%8,%9}, {%0,%1,%2,%3};"
        : "+f"(c[0]), "+f"(c[1]), "+f"(c[2]), "+f"(c[3])
        : "r"(a[0]), "r"(a[1]), "r"(a[2]), "r"(a[3]), "r"(b0), "r"(b1));
}
#define CP16(dst, src) \
    asm volatile("cp.async.cg.shared.global [%0], [%1], 16;" \
        :: "r"(dst), "l"(src))
#define CP_COMMIT() asm volatile("cp.async.commit_group;" ::: "memory")
#define CP_WAIT1()  asm volatile("cp.async.wait_group 1;" ::: "memory")
#define CP_WAIT0()  asm volatile("cp.async.wait_group 0;" ::: "memory")

__device__ __forceinline__ uint32_t pack2bf(float x, float y) {
    __nv_bfloat162 t = __floats2bfloat162_rn(x, y);
    return *(uint32_t*)&t;
}
__device__ __forceinline__ float bf_res(float x) {       // x - bf16(x)
    return x - __bfloat162float(__float2bfloat16_rn(x));
}
__device__ __forceinline__ uint32_t pack2h(float x, float y) {
    __half2 t = __floats2half2_rn(x, y);
    return *(uint32_t*)&t;
}
__device__ __forceinline__ float h_res(float x) {        // x - fp16(x)
    return x - __half2float(__float2half_rn(x));
}

// ---------------------------------------------------------------------------
// Kernel -1: RoPE table build. fp64 once per (t,j).
// ---------------------------------------------------------------------------
__global__ void rope_table_kernel()
{
    const int t = blockIdx.x;
    const int j = threadIdx.x;
    const double theta = exp(-(double)j * (9.210340371976184 / 64.0));
    double sd, cd;
    sincos((double)t * theta, &sd, &cd);
    g_rc[t * 64 + j] = (float)cd;
    g_rs[t * 64 + j] = (float)sd;
}

// ---------------------------------------------------------------------------
// Kernel 0: fused converters.
// ---------------------------------------------------------------------------
__global__ void convert_all_kernel(const float* __restrict__ x,
                                   const float* __restrict__ Wq,
                                   const float* __restrict__ Wk,
                                   const float* __restrict__ Wv,
                                   const float* __restrict__ Wo)
{
    const int i = blockIdx.x * 256 + threadIdx.x;
    const int kind = blockIdx.y;
    if (kind <= 2) {
        const float* src; __nv_bfloat16* hi; __nv_bfloat16* lo; int n4;
        if (kind == 0)      { src = x;  hi = g_xh;  lo = g_xl;  n4 = MROWS * DIM / 4; }
        else if (kind == 1) { src = Wq; hi = g_wqh; lo = g_wql; n4 = DIM * DIM / 4; }
        else                { src = Wk; hi = g_wkh; lo = g_wkl; n4 = DIM * DIM / 4; }
        if (i >= n4) return;
        float4 v = ((const float4*)src)[i];
        ((uint2*)hi)[i] = make_uint2(pack2bf(v.x, v.y), pack2bf(v.z, v.w));
        ((uint2*)lo)[i] = make_uint2(pack2bf(bf_res(v.x), bf_res(v.y)),
                                     pack2bf(bf_res(v.z), bf_res(v.w)));
    } else if (kind == 3) {
        const int n4 = MROWS * DIM / 4;
        if (i >= n4) return;
        float4 v = ((const float4*)x)[i];
        ((uint2*)g_xf)[i] = make_uint2(pack2h(v.x, v.y), pack2h(v.z, v.w));
    } else {
        const float* src; __half* hi; __half* lo;
        if (kind == 4) { src = Wv; hi = g_wvh; lo = g_wvl; }
        else           { src = Wo; hi = g_woh; lo = g_wol; }
        const int n4 = DIM * DIM / 4;
        if (i >= n4) return;
        float4 v = ((const float4*)src)[i];
        float a = v.x * WSCALE, b = v.y * WSCALE;
        float c = v.z * WSCALE, d = v.w * WSCALE;
        ((uint2*)hi)[i] = make_uint2(pack2h(a, b), pack2h(c, d));
        ((uint2*)lo)[i] = make_uint2(pack2h(h_res(a), h_res(b)),
                                     pack2h(h_res(c), h_res(d)));
    }
}

// ===========================================================================
// Tiling constants
// ===========================================================================
// bf16x3 QK path: KC=32, 4 matrices, 80B rows
#define KC 32
#define NKC (KDIM / KC)            // 64
#define ROWB 80
#define MAT 10240                  // 128*80
#define STG (4 * MAT)              // 40960
// fp16x2 path: KC=64, 3 matrices, 144B rows
#define KC2 64
#define NKC2 (KDIM / KC2)          // 32
#define ROWB2 144
#define MAT2 (128 * ROWB2)         // 18432
#define STG2 (3 * MAT2)            // 55296
#define P_SMEM_BYTES (2 * STG2)    // 110592 (covers both paths; epilogue 67.6KB)

// ---------------------------------------------------------------------------
// fp16x2 GEMM core, KC=64: acc += Af[M,K] x (Wh+Wl)[N,K]^T  (2 MMA passes)
// ---------------------------------------------------------------------------
__device__ __forceinline__ void f16x2_core64(const __half* __restrict__ Af,
                                             const __half* __restrict__ Wh,
                                             const __half* __restrict__ Wl,
                                             uint32_t sb, int tid,
                                             int m0, int n0,
                                             float acc[2][8][4])
{
    const int crow  = tid >> 1;
    const int chalf = tid & 1;
    const size_t aoff = (size_t)(m0 + crow) * KDIM + chalf * 32;
    const size_t boff = (size_t)(n0 + crow) * KDIM + chalf * 32;
    const uint32_t sto = (uint32_t)(crow * ROWB2 + chalf * 64);

    auto issue = [&](int kc, int buf) {
        const uint32_t st = sb + buf * STG2 + sto;
        const size_t ko = (size_t)kc * KC2;
#pragma unroll
        for (int c = 0; c < 4; ++c) {
            CP16(st + c * 16,            Af + aoff + ko + c * 8);
            CP16(st + MAT2 + c * 16,     Wh + boff + ko + c * 8);
            CP16(st + 2 * MAT2 + c * 16, Wl + boff + ko + c * 8);
        }
        CP_COMMIT();
    };

    const int wid  = tid >> 5;
    const int lane = tid & 31;
    const int wm = wid & 3;
    const int wn = wid >> 2;
    const int r   = lane & 7;
    const int sel = lane >> 3;
    const uint32_t aBase = (uint32_t)((wm * 32 + r + (sel & 1) * 8) * ROWB2 +
                                      (sel >> 1) * 16);
    const uint32_t bBase = (uint32_t)((wn * 64 + r + (sel >> 1) * 8) * ROWB2 +
                                      (sel & 1) * 16);

    issue(0, 0);
    for (int kc = 0; kc < NKC2; ++kc) {
        const int cur = kc & 1;
        if (kc + 1 < NKC2) { issue(kc + 1, cur ^ 1); CP_WAIT1(); }
        else               { CP_WAIT0(); }
        __syncthreads();

        const uint32_t stage = sb + cur * STG2;
#pragma unroll
        for (int ks = 0; ks < 4; ++ks) {
            const uint32_t koff = ks * 32;
            uint32_t ah[2][4];
#pragma unroll
            for (int i = 0; i < 2; ++i)
                ldsm4(stage + aBase + i * (16 * ROWB2) + koff, ah[i]);
#pragma unroll
            for (int j = 0; j < 4; ++j) {
                const uint32_t bA = stage + MAT2 + bBase + j * (16 * ROWB2) + koff;
                uint32_t bh[4], bl[4];
                ldsm4(bA, bh);
                ldsm4(bA + MAT2, bl);
                mma16816h(acc[0][j * 2 + 0], ah[0], bh[0], bh[1]);
                mma16816h(acc[0][j * 2 + 1], ah[0], bh[2], bh[3]);
                mma16816h(acc[1][j * 2 + 0], ah[1], bh[0], bh[1]);
                mma16816h(acc[1][j * 2 + 1], ah[1], bh[2], bh[3]);
                mma16816h(acc[0][j * 2 + 0], ah[0], bl[0], bl[1]);
                mma16816h(acc[0][j * 2 + 1], ah[0], bl[2], bl[3]);
                mma16816h(acc[1][j * 2 + 0], ah[1], bl[0], bl[1]);
                mma16816h(acc[1][j * 2 + 1], ah[1], bl[2], bl[3]);
            }
        }
        __syncthreads();
    }
}

// ===========================================================================
// Merged projection kernel. grid = (16, 32, 3).
// z in {0,1}: Q/K via bf16x3 KC=32 + fused rope epilogue (bf16 hi/lo out).
// z == 2:    V via fp16x2 KC=64 (fp16 hi/lo out).
// ===========================================================================
__global__ __launch_bounds__(256, 2)
void proj_kernel(const __nv_bfloat16* __restrict__ Ah,
                 const __nv_bfloat16* __restrict__ Al,
                 const __nv_bfloat16* __restrict__ Wqh,
                 const __nv_bfloat16* __restrict__ Wql,
                 const __nv_bfloat16* __restrict__ Wkh,
                 const __nv_bfloat16* __restrict__ Wkl,
                 const __half* __restrict__ xf,
                 const __half* __restrict__ wvh,
                 const __half* __restrict__ wvl,
                 const float* __restrict__ sqk)
{
    extern __shared__ char sm[];
    const uint32_t sb = smem_u32(sm);
    const int tid  = threadIdx.x;
    const int wid  = tid >> 5;
    const int lane = tid & 31;
    const int m0   = blockIdx.y * 128;
    const int n0   = blockIdx.x * 128;

    const int wm = wid & 3;
    const int wn = wid >> 2;

    if (blockIdx.z == 2) {
        // ------------------- V projection (fp16x2, KC=64) -------------------
        float acc[2][8][4];
#pragma unroll
        for (int i = 0; i < 2; i++)
#pragma unroll
            for (int j = 0; j < 8; j++)
#pragma unroll
                for (int t = 0; t < 4; t++) acc[i][j][t] = 0.f;

        f16x2_core64(xf, wvh, wvl, sb, tid, m0, n0, acc);

#pragma unroll
        for (int i = 0; i < 2; ++i) {
            const int mrow = m0 + wm * 32 + i * 16 + (lane >> 2);
            const int b = mrow >> 11;
            const int t = mrow & 2047;
#pragma unroll
            for (int j = 0; j < 8; ++j) {
                const int ncol = n0 + wn * 64 + j * 8 + 2 * (lane & 3);
                const int h = ncol >> 7;
                const int d = ncol & 127;
                const size_t base =
                    (((size_t)(b * NH + h)) * TSEQ + t) * HD + d;
                const float v0 = acc[i][j][0] * INV_WSCALE;
                const float v1 = acc[i][j][1] * INV_WSCALE;
                const float v2 = acc[i][j][2] * INV_WSCALE;
                const float v3 = acc[i][j][3] * INV_WSCALE;
                *(uint32_t*)&g_vh[base] = pack2h(v0, v1);
                *(uint32_t*)&g_vl[base] = pack2h(h_res(v0), h_res(v1));
                *(uint32_t*)&g_vh[base + (size_t)8 * HD] = pack2h(v2, v3);
                *(uint32_t*)&g_vl[base + (size_t)8 * HD] =
                    pack2h(h_res(v2), h_res(v3));
            }
        }
        return;
    }

    // ---------------------- Q/K projection (bf16x3, KC=32) ------------------
    const int isQ = (blockIdx.z == 0);
    const __nv_bfloat16* Bh = isQ ? Wqh : Wkh;
    const __nv_bfloat16* Bl = isQ ? Wql : Wkl;

    const int crow  = tid >> 1;
    const int chalf = tid & 1;
    const size_t aoff = (size_t)(m0 + crow) * KDIM + chalf * 16;
    const size_t boff = (size_t)(n0 + crow) * KDIM + chalf * 16;
    const uint32_t sto = (uint32_t)(crow * ROWB + chalf * 32);

    auto issue = [&](int kc, int buf) {
        const uint32_t st = sb + buf * STG + sto;
        const size_t ko = (size_t)kc * KC;
        CP16(st,                 Ah + aoff + ko);
        CP16(st + 16,            Ah + aoff + ko + 8);
        CP16(st + MAT,           Al + aoff + ko);
        CP16(st + MAT + 16,      Al + aoff + ko + 8);
        CP16(st + 2 * MAT,       Bh + boff + ko);
        CP16(st + 2 * MAT + 16,  Bh + boff + ko + 8);
        CP16(st + 3 * MAT,       Bl + boff + ko);
        CP16(st + 3 * MAT + 16,  Bl + boff + ko + 8);
        CP_COMMIT();
    };

    const int r   = lane & 7;
    const int sel = lane >> 3;
    const uint32_t aBase = (uint32_t)((wm * 32 + r + (sel & 1) * 8) * ROWB +
                                      (sel >> 1) * 16);
    const uint32_t bBase = (uint32_t)((wn * 64 + r + (sel >> 1) * 8) * ROWB +
                                      (sel & 1) * 16);

    float acc[2][8][4];
#pragma unroll
    for (int i = 0; i < 2; i++)
#pragma unroll
        for (int j = 0; j < 8; j++)
#pragma unroll
            for (int t = 0; t < 4; t++) acc[i][j][t] = 0.f;

    issue(0, 0);
    for (int kc = 0; kc < NKC; ++kc) {
        const int cur = kc & 1;
        if (kc + 1 < NKC) { issue(kc + 1, cur ^ 1); CP_WAIT1(); }
        else              { CP_WAIT0(); }
        __syncthreads();

        const uint32_t stage = sb + cur * STG;
#pragma unroll
        for (int ks = 0; ks < 2; ++ks) {
            const uint32_t koff = ks * 32;
            uint32_t ah[2][4], al[2][4];
#pragma unroll
            for (int i = 0; i < 2; ++i) {
                const uint32_t aA = stage + aBase + i * (16 * ROWB) + koff;
                ldsm4(aA, ah[i]);
                ldsm4(aA + MAT, al[i]);
            }
#pragma unroll
            for (int j = 0; j < 4; ++j) {
                const uint32_t bA = stage + 2 * MAT + bBase + j * (16 * ROWB) + koff;
                uint32_t bh[4], bl[4];
                ldsm4(bA, bh);
                ldsm4(bA + MAT, bl);
                mma16816(acc[0][j * 2 + 0], ah[0], bh[0], bh[1]);
                mma16816(acc[0][j * 2 + 1], ah[0], bh[2], bh[3]);
                mma16816(acc[1][j * 2 + 0], ah[1], bh[0], bh[1]);
                mma16816(acc[1][j * 2 + 1], ah[1], bh[2], bh[3]);
                mma16816(acc[0][j * 2 + 0], ah[0], bl[0], bl[1]);
                mma16816(acc[0][j * 2 + 1], ah[0], bl[2], bl[3]);
                mma16816(acc[1][j * 2 + 0], ah[1], bl[0], bl[1]);
                mma16816(acc[1][j * 2 + 1], ah[1], bl[2], bl[3]);
                mma16816(acc[0][j * 2 + 0], al[0], bh[0], bh[1]);
                mma16816(acc[0][j * 2 + 1], al[0], bh[2], bh[3]);
                mma16816(acc[1][j * 2 + 0], al[1], bh[0], bh[1]);
                mma16816(acc[1][j * 2 + 1], al[1], bh[2], bh[3]);
            }
        }
        __syncthreads();
    }

    // ---- fused epilogue: stage fp32 tile, rope, write bf16 hi/lo ----
    float* smf = (float*)sm;   // [128][132]
#pragma unroll
    for (int i = 0; i < 2; ++i) {
        const int lr = wm * 32 + i * 16 + (lane >> 2);
        const int lc = wn * 64;
#pragma unroll
        for (int j = 0; j < 8; ++j) {
            const int c0 = lc + j * 8 + 2 * (lane & 3);
            smf[lr * 132 + c0]           = acc[i][j][0];
            smf[lr * 132 + c0 + 1]       = acc[i][j][1];
            smf[(lr + 8) * 132 + c0]     = acc[i][j][2];
            smf[(lr + 8) * 132 + c0 + 1] = acc[i][j][3];
        }
    }
    __syncthreads();

    const int h  = n0 >> 7;
    const int jj = tid & 63;                 // loop-invariant j
    const float AT = isQ ? ATTN_SCALE : 1.0f;
    const float s1 = sqk[h * HD + jj]      * RESTORE_SCALE * AT;
    const float s2 = sqk[h * HD + 64 + jj] * RESTORE_SCALE * AT;
    __nv_bfloat16* oh = isQ ? g_qh : g_kh;
    __nv_bfloat16* ol = isQ ? g_ql : g_kl;

#pragma unroll
    for (int k2 = 0; k2 < 32; ++k2) {
        const int lr = k2 * 4 + (tid >> 6);  // local row 0..127
        const int m  = m0 + lr;
        const int bb = m >> 11;
        const int t  = m & 2047;
        const float v1 = smf[lr * 132 + jj];
        const float v2 = smf[lr * 132 + 64 + jj];
        const float c  = g_rc[t * 64 + jj];
        const float sn = g_rs[t * 64 + jj];
        const float o1 = (v1 * c - v2 * sn) * s1;
        const float o2 = (v1 * sn + v2 * c) * s2;
        const size_t base = (((size_t)(bb * NH + h)) * TSEQ + t) * HD;
        oh[base + jj]      = __float2bfloat16_rn(o1);
        ol[base + jj]      = __float2bfloat16_rn(bf_res(o1));
        oh[base + 64 + jj] = __float2bfloat16_rn(o2);
        ol[base + 64 + jj] = __float2bfloat16_rn(bf_res(o2));
    }
}

// ===========================================================================
// Output projection: y = att @ (Wo*64)^T  (fp16x2, KC=64).
// y carries *64 scale; row L2-norm cancels it exactly.
// ===========================================================================
__global__ __launch_bounds__(256, 2)
void out_proj_kernel(const __half* __restrict__ af,
                     const __half* __restrict__ woh,
                     const __half* __restrict__ wol,
                     float* __restrict__ y)
{
    extern __shared__ char sm[];
    const uint32_t sb = smem_u32(sm);
    const int tid  = threadIdx.x;
    const int wid  = tid >> 5;
    const int lane = tid & 31;
    const int m0   = blockIdx.y * 128;
    const int n0   = blockIdx.x * 128;
    const int wm = wid & 3;
    const int wn = wid >> 2;

    float acc[2][8][4];
#pragma unroll
    for (int i = 0; i < 2; i++)
#pragma unroll
        for (int j = 0; j < 8; j++)
#pragma unroll
            for (int t = 0; t < 4; t++) acc[i][j][t] = 0.f;

    f16x2_core64(af, woh, wol, sb, tid, m0, n0, acc);

#pragma unroll
    for (int i = 0; i < 2; ++i) {
        const int mrow = m0 + wm * 32 + i * 16 + (lane >> 2);
#pragma unroll
        for (int j = 0; j < 8; ++j) {
            const int ncol = n0 + wn * 64 + j * 8 + 2 * (lane & 3);
            float* dst = &y[(size_t)mrow * DIM + ncol];
            *(float2*)dst = make_float2(acc[i][j][0], acc[i][j][1]);
            *(float2*)(dst + (size_t)8 * DIM) =
                make_float2(acc[i][j][2], acc[i][j][3]);
        }
    }
}

// ===========================================================================
// Kernel 3: causal flash attention. BR=64 (4 warps), BC=32, double-buffered,
// 128 threads, 2 CTAs/SM.  QK^T bf16x3; PV fp16x2 (Ph * (Vh+Vl)).
// ===========================================================================
#define FB_ROWB 272                      // 128 elems * 2B + 16B pad
#define F_QH 0
#define F_QL 17408                       // 64*272
#define F_KV 34816
#define F_KVSTG 34816                    // per stage: Kh,Kl,Vh,Vl @ 8704 each
#define F_SMEM_BYTES (F_KV + 2 * F_KVSTG)   // 104,448

__global__ __launch_bounds__(128, 2)
void flash_hmma_kernel()
{
    extern __shared__ char sm[];
    const uint32_t sb = smem_u32(sm);
    const int tid  = threadIdx.x;
    const int w    = tid >> 5;
    const int lane = tid & 31;
    const int i0   = (int)(gridDim.x - 1 - blockIdx.x) * 64;
    const int bh   = blockIdx.y;
    const int b    = bh >> 4;
    const int h    = bh & 15;
    const size_t kvbase = (size_t)bh * TSEQ * HD;

    // ---- prologue: Q (hi+lo) and KV tile 0 ----
    {
        const size_t qgbase = kvbase + (size_t)i0 * HD;
#pragma unroll
        for (int it = 0; it < 16; ++it) {
            const int idx = (it & 7) * 128 + tid;
            const int row = idx >> 4;
            const int ch  = idx & 15;
            const uint32_t dst = sb + ((it < 8) ? F_QH : F_QL) +
                                 row * FB_ROWB + ch * 16;
            const __nv_bfloat16* src = (it < 8) ? g_qh : g_ql;
            CP16(dst, src + qgbase + (size_t)row * HD + ch * 8);
        }
#pragma unroll
        for (int it = 0; it < 16; ++it) {
            const int mat = it >> 2;
            const int idx = (it & 3) * 128 + tid;
            const int row = idx >> 4;
            const int ch  = idx & 15;
            const uint32_t dst = sb + F_KV + mat * 8704 +
                                 row * FB_ROWB + ch * 16;
            const void* src =
                (mat == 0) ? (const void*)(g_kh + kvbase + (size_t)row * HD + ch * 8)
              : (mat == 1) ? (const void*)(g_kl + kvbase + (size_t)row * HD + ch * 8)
              : (mat == 2) ? (const void*)(g_vh + kvbase + (size_t)row * HD + ch * 8)
                           : (const void*)(g_vl + kvbase + (size_t)row * HD + ch * 8);
            CP16(dst, src);
        }
        CP_COMMIT();
    }

    const int r   = lane & 7;
    const int sel = lane >> 3;
    const uint32_t qBase = (uint32_t)((w * 16 + r + (sel & 1) * 8) * FB_ROWB +
                                      (sel >> 1) * 16);
    const uint32_t kBase = (uint32_t)((r + (sel >> 1) * 8) * FB_ROWB +
                                      (sel & 1) * 16);
    const uint32_t vBase = (uint32_t)(((sel & 1) * 8 + r) * FB_ROWB +
                                      (sel >> 1) * 16);

    float o[16][4];
#pragma unroll
    for (int i = 0; i < 16; i++)
#pragma unroll
        for (int t = 0; t < 4; t++) o[i][t] = 0.f;
    float m1 = -1e30f, m2 = -1e30f, l1 = 0.f, l2 = 0.f;
    const int grow1 = i0 + w * 16 + (lane >> 2);
    const int grow2 = grow1 + 8;

    const int ntiles = (i0 >> 5) + 2;
    for (int jt = 0; jt < ntiles; ++jt) {
        const int j0 = jt * 32;
        if (jt + 1 < ntiles) {
            const int nj0 = j0 + 32;
            const uint32_t stg = sb + F_KV + ((jt + 1) & 1) * F_KVSTG;
#pragma unroll
            for (int it = 0; it < 16; ++it) {
                const int mat = it >> 2;
                const int idx = (it & 3) * 128 + tid;
                const int row = idx >> 4;
                const int ch  = idx & 15;
                const uint32_t dst = stg + mat * 8704 + row * FB_ROWB + ch * 16;
                const void* src =
                    (mat == 0) ? (const void*)(g_kh + kvbase + (size_t)(nj0 + row) * HD + ch * 8)
                  : (mat == 1) ? (const void*)(g_kl + kvbase + (size_t)(nj0 + row) * HD + ch * 8)
                  : (mat == 2) ? (const void*)(g_vh + kvbase + (size_t)(nj0 + row) * HD + ch * 8)
                               : (const void*)(g_vl + kvbase + (size_t)(nj0 + row) * HD + ch * 8);
                CP16(dst, src);
            }
            CP_COMMIT();
            CP_WAIT1();
        } else {
            CP_WAIT0();
        }
        __syncthreads();

        const uint32_t stg = sb + F_KV + (jt & 1) * F_KVSTG;
        const uint32_t KH = stg, KL = stg + 8704;
        const uint32_t VH = stg + 17408, VL = stg + 26112;

        // ---- S = Q K^T (bf16x3), per warp 16x32 ----
        float s[4][4];
#pragma unroll
        for (int i = 0; i < 4; i++)
#pragma unroll
            for (int t = 0; t < 4; t++) s[i][t] = 0.f;

#pragma unroll
        for (int kk = 0; kk < 8; ++kk) {
            uint32_t ah[4], al[4];
            ldsm4(sb + F_QH + qBase + kk * 32, ah);
            ldsm4(sb + F_QL + qBase + kk * 32, al);
#pragma unroll
            for (int j = 0; j < 2; ++j) {
                const uint32_t kA = kBase + j * (16 * FB_ROWB) + kk * 32;
                uint32_t bhf[4], blf[4];
                ldsm4(KH + kA, bhf);
                ldsm4(KL + kA, blf);
                mma16816(s[j * 2 + 0], ah, bhf[0], bhf[1]);
                mma16816(s[j * 2 + 1], ah, bhf[2], bhf[3]);
                mma16816(s[j * 2 + 0], ah, blf[0], blf[1]);
                mma16816(s[j * 2 + 1], ah, blf[2], blf[3]);
                mma16816(s[j * 2 + 0], al, bhf[0], bhf[1]);
                mma16816(s[j * 2 + 1], al, bhf[2], bhf[3]);
            }
        }

        // ---- causal mask ----
        if (j0 + 31 > i0 + w * 16) {
#pragma unroll
            for (int t8 = 0; t8 < 4; ++t8) {
                const int gcol = j0 + t8 * 8 + 2 * (lane & 3);
                if (gcol > grow1)     s[t8][0] = -1e30f;
                if (gcol + 1 > grow1) s[t8][1] = -1e30f;
                if (gcol > grow2)     s[t8][2] = -1e30f;
                if (gcol + 1 > grow2) s[t8][3] = -1e30f;
            }
        }

        // ---- online softmax ----
        float nm1 = m1, nm2 = m2;
#pragma unroll
        for (int t8 = 0; t8 < 4; ++t8) {
            nm1 = fmaxf(nm1, fmaxf(s[t8][0], s[t8][1]));
            nm2 = fmaxf(nm2, fmaxf(s[t8][2], s[t8][3]));
        }
        nm1 = fmaxf(nm1, __shfl_xor_sync(0xffffffffu, nm1, 1));
        nm1 = fmaxf(nm1, __shfl_xor_sync(0xffffffffu, nm1, 2));
        nm2 = fmaxf(nm2, __shfl_xor_sync(0xffffffffu, nm2, 1));
        nm2 = fmaxf(nm2, __shfl_xor_sync(0xffffffffu, nm2, 2));
        const float a1 = __expf(m1 - nm1);
        const float a2 = __expf(m2 - nm2);
        float r1 = 0.f, r2 = 0.f;
#pragma unroll
        for (int t8 = 0; t8 < 4; ++t8) {
            s[t8][0] = __expf(s[t8][0] - nm1);
            s[t8][1] = __expf(s[t8][1] - nm1);
            s[t8][2] = __expf(s[t8][2] - nm2);
            s[t8][3] = __expf(s[t8][3] - nm2);
            r1 += s[t8][0] + s[t8][1];
            r2 += s[t8][2] + s[t8][3];
        }
        r1 += __shfl_xor_sync(0xffffffffu, r1, 1);
        r1 += __shfl_xor_sync(0xffffffffu, r1, 2);
        r2 += __shfl_xor_sync(0xffffffffu, r2, 1);
        r2 += __shfl_xor_sync(0xffffffffu, r2, 2);
        l1 = l1 * a1 + r1;
        l2 = l2 * a2 + r2;
        m1 = nm1; m2 = nm2;
#pragma unroll
        for (int i = 0; i < 16; ++i) {
            o[i][0] *= a1; o[i][1] *= a1;
            o[i][2] *= a2; o[i][3] *= a2;
        }

        // ---- O += Ph (Vh + Vl), fp16, 2 passes ----
#pragma unroll
        for (int kk = 0; kk < 2; ++kk) {
            uint32_t pah[4];
            {
                const float* p0 = s[2 * kk];
                const float* p1 = s[2 * kk + 1];
                pah[0] = pack2h(p0[0], p0[1]);
                pah[1] = pack2h(p0[2], p0[3]);
                pah[2] = pack2h(p1[0], p1[1]);
                pah[3] = pack2h(p1[2], p1[3]);
            }
#pragma unroll
            for (int dc = 0; dc < 4; ++dc) {
                uint32_t vh[2][4], vl[2][4];
#pragma unroll
                for (int u = 0; u < 2; ++u) {
                    const uint32_t vA = vBase + kk * (16 * FB_ROWB) +
                                        (dc * 2 + u) * 32;
                    ldsm4t(VH + vA, vh[u]);
                    ldsm4t(VL + vA, vl[u]);
                }
#pragma unroll
                for (int u = 0; u < 2; ++u) {
                    mma16816h(o[(dc * 2 + u) * 2 + 0], pah, vh[u][0], vh[u][1]);
                    mma16816h(o[(dc * 2 + u) * 2 + 1], pah, vh[u][2], vh[u][3]);
                }
#pragma unroll
                for (int u = 0; u < 2; ++u) {
                    mma16816h(o[(dc * 2 + u) * 2 + 0], pah, vl[u][0], vl[u][1]);
                    mma16816h(o[(dc * 2 + u) * 2 + 1], pah, vl[u][2], vl[u][3]);
                }
            }
        }
        __syncthreads();
    }

    // ---- epilogue: att as fp16 single ----
    const float inv1 = 1.0f / l1;
    const float inv2 = 1.0f / l2;
#pragma unroll
    for (int ot = 0; ot < 16; ++ot) {
        const int cold = ot * 8 + 2 * (lane & 3);
        const size_t i1 = ((size_t)(b * TSEQ + grow1)) * DIM + h * HD + cold;
        const size_t i2 = ((size_t)(b * TSEQ + grow2)) * DIM + h * HD + cold;
        *(uint32_t*)&g_af[i1] = pack2h(o[ot][0] * inv1, o[ot][1] * inv1);
        *(uint32_t*)&g_af[i2] = pack2h(o[ot][2] * inv2, o[ot][3] * inv2);
    }
}

// ---------------------------------------------------------------------------
// Kernel 5: per-row L2 normalization of y (in place on d_out)
// ---------------------------------------------------------------------------
__global__ void norm_kernel(float* __restrict__ y)
{
    const int row = blockIdx.x;
    float4* p = (float4*)(y + (size_t)row * DIM);
    float ss = 0.f;
#pragma unroll
    for (int i = threadIdx.x; i < DIM / 4; i += 256) {
        float4 v = p[i];
        ss += v.x * v.x + v.y * v.y + v.z * v.z + v.w * v.w;
    }
    ss += __shfl_xor_sync(0xffffffffu, ss, 16);
    ss += __shfl_xor_sync(0xffffffffu, ss, 8);
    ss += __shfl_xor_sync(0xffffffffu, ss, 4);
    ss += __shfl_xor_sync(0xffffffffu, ss, 2);
    ss += __shfl_xor_sync(0xffffffffu, ss, 1);
    __shared__ float red[8];
    if ((threadIdx.x & 31) == 0) red[threadIdx.x >> 5] = ss;
    __syncthreads();
    float tot = red[0] + red[1] + red[2] + red[3] +
                red[4] + red[5] + red[6] + red[7];
    const float inv = 1.0f / fmaxf(sqrtf(tot), 1e-12f);
#pragma unroll
    for (int i = threadIdx.x; i < DIM / 4; i += 256) {
        float4 v = p[i];
        v.x *= inv; v.y *= inv; v.z *= inv; v.w *= inv;
        p[i] = v;
    }
}

// ---------------------------------------------------------------------------
// Launch
// ---------------------------------------------------------------------------
extern "C" void kernel_launch(void* const* d_in, const int* in_sizes, int n_in,
                              void* d_out, int out_size)
{
    const float* x   = (const float*)d_in[0];
    const float* Wq  = (const float*)d_in[1];
    const float* Wk  = (const float*)d_in[2];
    const float* Wv  = (const float*)d_in[3];
    const float* Wo  = (const float*)d_in[4];
    const float* sqk = (const float*)d_in[5];
    float* y = (float*)d_out;

    __nv_bfloat16 *xh, *xl, *wqh, *wql, *wkh, *wkl;
    __half *xf, *wvh, *wvl, *woh, *wol, *af;
    cudaGetSymbolAddress((void**)&xh,  g_xh);
    cudaGetSymbolAddress((void**)&xl,  g_xl);
    cudaGetSymbolAddress((void**)&wqh, g_wqh);
    cudaGetSymbolAddress((void**)&wql, g_wql);
    cudaGetSymbolAddress((void**)&wkh, g_wkh);
    cudaGetSymbolAddress((void**)&wkl, g_wkl);
    cudaGetSymbolAddress((void**)&xf,  g_xf);
    cudaGetSymbolAddress((void**)&wvh, g_wvh);
    cudaGetSymbolAddress((void**)&wvl, g_wvl);
    cudaGetSymbolAddress((void**)&woh, g_woh);
    cudaGetSymbolAddress((void**)&wol, g_wol);
    cudaGetSymbolAddress((void**)&af,  g_af);

    cudaFuncSetAttribute(flash_hmma_kernel,
                         cudaFuncAttributeMaxDynamicSharedMemorySize,
                         F_SMEM_BYTES);
    cudaFuncSetAttribute(proj_kernel,
                         cudaFuncAttributeMaxDynamicSharedMemorySize,
                         P_SMEM_BYTES);
    cudaFuncSetAttribute(out_proj_kernel,
                         cudaFuncAttributeMaxDynamicSharedMemorySize,
                         P_SMEM_BYTES);

    rope_table_kernel<<<TSEQ, 64>>>();

    const int NX4 = MROWS * DIM / 4;   // largest convert
    convert_all_kernel<<<dim3((NX4 + 255) / 256, 6), 256>>>(x, Wq, Wk, Wv, Wo);

    proj_kernel<<<dim3(DIM / 128, MROWS / 128, 3), 256, P_SMEM_BYTES>>>(
        xh, xl, wqh, wql, wkh, wkl, xf, wvh, wvl, sqk);
    flash_hmma_kernel<<<dim3(TSEQ / 64, BATCH * NH), 128, F_SMEM_BYTES>>>();
    out_proj_kernel<<<dim3(DIM / 128, MROWS / 128), 256, P_SMEM_BYTES>>>(
        af, woh, wol, y);
    norm_kernel<<<MROWS, 256>>>(y);
}

// round 15
// speedup vs baseline: 1.2200x; 1.2200x over previous
#include <cuda_runtime.h>
#include <cuda_bf16.h>
#include <cuda_fp16.h>
#include <math.h>
#include <stdint.h>

// Problem constants
#define BATCH 2
#define TSEQ  2048
#define DIM   2048
#define NH    16
#define HD    128
#define MROWS (BATCH * TSEQ)      // 4096
#define KDIM  DIM                 // 2048
#define NELEM ((size_t)BATCH * NH * TSEQ * HD)   // 8.4M

#define RESTORE_SCALE 45.25483399593904f   // sqrt(2048)
#define ATTN_SCALE    11.313708498984761f  // sqrt(128)
#define WSCALE 64.0f
#define INV_WSCALE (1.0f / 64.0f)

// ---------------------------------------------------------------------------
// Scratch (device globals — allocation-free rule)
// ---------------------------------------------------------------------------
__device__ float g_q[NELEM];                 // [B,H,T,HD] fp32 (pre-rope)
__device__ float g_k[NELEM];
__device__ float g_v[NELEM];

// bf16 pairs (high-precision Q/K path)
__device__ __nv_bfloat16 g_xh[(size_t)MROWS * DIM], g_xl[(size_t)MROWS * DIM];
__device__ __nv_bfloat16 g_wqh[(size_t)DIM * DIM], g_wql[(size_t)DIM * DIM];
__device__ __nv_bfloat16 g_wkh[(size_t)DIM * DIM], g_wkl[(size_t)DIM * DIM];
__device__ __nv_bfloat16 g_qh[NELEM], g_ql[NELEM];   // roped+scaled q
__device__ __nv_bfloat16 g_kh[NELEM], g_kl[NELEM];   // roped+scaled k

// fp16 single path (V / att / out-proj)
__device__ __half g_xf[(size_t)MROWS * DIM];                 // x fp16
__device__ __half g_wvf[(size_t)DIM * DIM];                  // Wv*64 fp16
__device__ __half g_wof[(size_t)DIM * DIM];                  // Wo*64 fp16
__device__ __half g_vf[NELEM];                               // v fp16
__device__ __half g_af[(size_t)MROWS * DIM];                 // attn out fp16

// RoPE tables: cos/sin for (t, j), t in [0,2048), j in [0,64)
__device__ float g_rc[TSEQ * 64];
__device__ float g_rs[TSEQ * 64];

// ---------------------------------------------------------------------------
// PTX helpers (base sm_103 target safe: ldmatrix / mma.sync / cp.async)
// ---------------------------------------------------------------------------
__device__ __forceinline__ uint32_t smem_u32(const void* p) {
    uint32_t a;
    asm("{ .reg .u64 t; cvta.to.shared.u64 t, %1; cvt.u32.u64 %0, t; }"
        : "=r"(a) : "l"(p));
    return a;
}
__device__ __forceinline__ void ldsm4(uint32_t addr, uint32_t r[4]) {
    asm volatile("ldmatrix.sync.aligned.m8n8.x4.shared.b16 {%0,%1,%2,%3}, [%4];"
        : "=r"(r[0]), "=r"(r[1]), "=r"(r[2]), "=r"(r[3]) : "r"(addr));
}
__device__ __forceinline__ void ldsm4t(uint32_t addr, uint32_t r[4]) {
    asm volatile("ldmatrix.sync.aligned.m8n8.x4.trans.shared.b16 {%0,%1,%2,%3}, [%4];"
        : "=r"(r[0]), "=r"(r[1]), "=r"(r[2]), "=r"(r[3]) : "r"(addr));
}
__device__ __forceinline__ void mma16816(float c[4], const uint32_t a[4],
                                         uint32_t b0, uint32_t b1) {
    asm volatile(
        "mma.sync.aligned.m16n8k16.row.col.f32.bf16.bf16.f32 "
        "{%0,%1,%2,%3}, {%4,%5,%6,%7}, {%8,%9}, {%0,%1,%2,%3};"
        : "+f"(c[0]), "+f"(c[1]), "+f"(c[2]), "+f"(c[3])
        : "r"(a[0]), "r"(a[1]), "r"(a[2]), "r"(a[3]), "r"(b0), "r"(b1));
}
__device__ __forceinline__ void mma16816h(float c[4], const uint32_t a[4],
                                          uint32_t b0, uint32_t b1) {
    asm volatile(
        "mma.sync.aligned.m16n8k16.row.col.f32.f16.f16.f32 "
        "{%0,%1,%2,%3}, {%4,%5,%6,%7}, {%8,%9}, {%0,%1,%2,%3};"
        : "+f"(c[0]), "+f"(c[1]), "+f"(c[2]), "+f"(c[3])
        : "r"(a[0]), "r"(a[1]), "r"(a[2]), "r"(a[3]), "r"(b0), "r"(b1));
}
#define CP16(dst, src) \
    asm volatile("cp.async.cg.shared.global [%0], [%1], 16;" \
        :: "r"(dst), "l"(src))
#define CP_COMMIT() asm volatile("cp.async.commit_group;" ::: "memory")
#define CP_WAIT1()  asm volatile("cp.async.wait_group 1;" ::: "memory")
#define CP_WAIT0()  asm volatile("cp.async.wait_group 0;" ::: "memory")

__device__ __forceinline__ uint32_t pack2bf(float x, float y) {
    __nv_bfloat162 t = __floats2bfloat162_rn(x, y);
    return *(uint32_t*)&t;
}
__device__ __forceinline__ float bf_res(float x) {       // x - bf16(x)
    return x - __bfloat162float(__float2bfloat16_rn(x));
}
__device__ __forceinline__ uint32_t pack2h(float x, float y) {
    __half2 t = __floats2half2_rn(x, y);
    return *(uint32_t*)&t;
}

// ---------------------------------------------------------------------------
// Kernel -1: RoPE table build. fp64 once per (t,j).
// ---------------------------------------------------------------------------
__global__ void rope_table_kernel()
{
    const int t = blockIdx.x;
    const int j = threadIdx.x;
    const double theta = exp(-(double)j * (9.210340371976184 / 64.0));
    double sd, cd;
    sincos((double)t * theta, &sd, &cd);
    g_rc[t * 64 + j] = (float)cd;
    g_rs[t * 64 + j] = (float)sd;
}

// ---------------------------------------------------------------------------
// Kernel 0: fused converters.
// y=0: x->bf16 pair, y=1: Wq, y=2: Wk (bf16 pairs)
// y=3: x->fp16 single, y=4: Wv*64 fp16 single, y=5: Wo*64 fp16 single
// ---------------------------------------------------------------------------
__global__ void convert_all_kernel(const float* __restrict__ x,
                                   const float* __restrict__ Wq,
                                   const float* __restrict__ Wk,
                                   const float* __restrict__ Wv,
                                   const float* __restrict__ Wo)
{
    const int i = blockIdx.x * 256 + threadIdx.x;
    const int kind = blockIdx.y;
    if (kind <= 2) {
        const float* src; __nv_bfloat16* hi; __nv_bfloat16* lo; int n4;
        if (kind == 0)      { src = x;  hi = g_xh;  lo = g_xl;  n4 = MROWS * DIM / 4; }
        else if (kind == 1) { src = Wq; hi = g_wqh; lo = g_wql; n4 = DIM * DIM / 4; }
        else                { src = Wk; hi = g_wkh; lo = g_wkl; n4 = DIM * DIM / 4; }
        if (i >= n4) return;
        float4 v = ((const float4*)src)[i];
        ((uint2*)hi)[i] = make_uint2(pack2bf(v.x, v.y), pack2bf(v.z, v.w));
        ((uint2*)lo)[i] = make_uint2(pack2bf(bf_res(v.x), bf_res(v.y)),
                                     pack2bf(bf_res(v.z), bf_res(v.w)));
    } else if (kind == 3) {
        const int n4 = MROWS * DIM / 4;
        if (i >= n4) return;
        float4 v = ((const float4*)x)[i];
        ((uint2*)g_xf)[i] = make_uint2(pack2h(v.x, v.y), pack2h(v.z, v.w));
    } else {
        const float* src; __half* dst;
        if (kind == 4) { src = Wv; dst = g_wvf; }
        else           { src = Wo; dst = g_wof; }
        const int n4 = DIM * DIM / 4;
        if (i >= n4) return;
        float4 v = ((const float4*)src)[i];
        ((uint2*)dst)[i] = make_uint2(pack2h(v.x * WSCALE, v.y * WSCALE),
                                      pack2h(v.z * WSCALE, v.w * WSCALE));
    }
}

// ===========================================================================
// GEMM A (bf16x3): Q and K projections (fp32 out). grid z in {0,1}.
// ===========================================================================
#define KC 32
#define NKC (KDIM / KC)            // 64
#define ROWB 80
#define MAT 10240                  // 128*80
#define STG (4 * MAT)              // 40960
#define G_SMEM_BYTES (2 * STG)     // 81920

__global__ __launch_bounds__(256, 2)
void gemm_bf16x3_kernel(const __nv_bfloat16* __restrict__ Ah,
                        const __nv_bfloat16* __restrict__ Al,
                        const __nv_bfloat16* __restrict__ W0h,
                        const __nv_bfloat16* __restrict__ W0l,
                        const __nv_bfloat16* __restrict__ W1h,
                        const __nv_bfloat16* __restrict__ W1l)
{
    extern __shared__ char sm[];
    const uint32_t sb = smem_u32(sm);
    const int tid  = threadIdx.x;
    const int wid  = tid >> 5;
    const int lane = tid & 31;
    const int m0   = blockIdx.y * 128;
    const int n0   = blockIdx.x * 128;

    const __nv_bfloat16* Bh = (blockIdx.z == 0) ? W0h : W1h;
    const __nv_bfloat16* Bl = (blockIdx.z == 0) ? W0l : W1l;
    float* out = (blockIdx.z == 0) ? g_q : g_k;

    const int crow  = tid >> 1;
    const int chalf = tid & 1;
    const size_t aoff = (size_t)(m0 + crow) * KDIM + chalf * 16;
    const size_t boff = (size_t)(n0 + crow) * KDIM + chalf * 16;
    const uint32_t sto = (uint32_t)(crow * ROWB + chalf * 32);

    auto issue = [&](int kc, int buf) {
        const uint32_t st = sb + buf * STG + sto;
        const size_t ko = (size_t)kc * KC;
        CP16(st,                 Ah + aoff + ko);
        CP16(st + 16,            Ah + aoff + ko + 8);
        CP16(st + MAT,           Al + aoff + ko);
        CP16(st + MAT + 16,      Al + aoff + ko + 8);
        CP16(st + 2 * MAT,       Bh + boff + ko);
        CP16(st + 2 * MAT + 16,  Bh + boff + ko + 8);
        CP16(st + 3 * MAT,       Bl + boff + ko);
        CP16(st + 3 * MAT + 16,  Bl + boff + ko + 8);
        CP_COMMIT();
    };

    const int wm = wid & 3;
    const int wn = wid >> 2;
    const int r   = lane & 7;
    const int sel = lane >> 3;
    const uint32_t aBase = (uint32_t)((wm * 32 + r + (sel & 1) * 8) * ROWB +
                                      (sel >> 1) * 16);
    const uint32_t bBase = (uint32_t)((wn * 64 + r + (sel >> 1) * 8) * ROWB +
                                      (sel & 1) * 16);

    float acc[2][8][4];
#pragma unroll
    for (int i = 0; i < 2; i++)
#pragma unroll
        for (int j = 0; j < 8; j++)
#pragma unroll
            for (int t = 0; t < 4; t++) acc[i][j][t] = 0.f;

    issue(0, 0);
    for (int kc = 0; kc < NKC; ++kc) {
        const int cur = kc & 1;
        if (kc + 1 < NKC) { issue(kc + 1, cur ^ 1); CP_WAIT1(); }
        else              { CP_WAIT0(); }
        __syncthreads();

        const uint32_t stage = sb + cur * STG;
#pragma unroll
        for (int ks = 0; ks < 2; ++ks) {
            const uint32_t koff = ks * 32;
            uint32_t ah[2][4], al[2][4];
#pragma unroll
            for (int i = 0; i < 2; ++i) {
                const uint32_t aA = stage + aBase + i * (16 * ROWB) + koff;
                ldsm4(aA, ah[i]);
                ldsm4(aA + MAT, al[i]);
            }
#pragma unroll
            for (int j = 0; j < 4; ++j) {
                const uint32_t bA = stage + 2 * MAT + bBase + j * (16 * ROWB) + koff;
                uint32_t bh[4], bl[4];
                ldsm4(bA, bh);
                ldsm4(bA + MAT, bl);
                mma16816(acc[0][j * 2 + 0], ah[0], bh[0], bh[1]);
                mma16816(acc[0][j * 2 + 1], ah[0], bh[2], bh[3]);
                mma16816(acc[1][j * 2 + 0], ah[1], bh[0], bh[1]);
                mma16816(acc[1][j * 2 + 1], ah[1], bh[2], bh[3]);
                mma16816(acc[0][j * 2 + 0], ah[0], bl[0], bl[1]);
                mma16816(acc[0][j * 2 + 1], ah[0], bl[2], bl[3]);
                mma16816(acc[1][j * 2 + 0], ah[1], bl[0], bl[1]);
                mma16816(acc[1][j * 2 + 1], ah[1], bl[2], bl[3]);
                mma16816(acc[0][j * 2 + 0], al[0], bh[0], bh[1]);
                mma16816(acc[0][j * 2 + 1], al[0], bh[2], bh[3]);
                mma16816(acc[1][j * 2 + 0], al[1], bh[0], bh[1]);
                mma16816(acc[1][j * 2 + 1], al[1], bh[2], bh[3]);
            }
        }
        __syncthreads();
    }

    // scatter epilogue to [B,H,T,HD]
#pragma unroll
    for (int i = 0; i < 2; ++i) {
        const int mrow = m0 + wm * 32 + i * 16 + (lane >> 2);
        const int b = mrow >> 11;
        const int t = mrow & 2047;
#pragma unroll
        for (int j = 0; j < 8; ++j) {
            const int ncol = n0 + wn * 64 + j * 8 + 2 * (lane & 3);
            const int h = ncol >> 7;
            const int d = ncol & 127;
            float* dst = &out[(((size_t)(b * NH + h)) * TSEQ + t) * HD + d];
            *(float2*)dst = make_float2(acc[i][j][0], acc[i][j][1]);
            *(float2*)(dst + (size_t)8 * HD) =
                make_float2(acc[i][j][2], acc[i][j][3]);
        }
    }
}

// ===========================================================================
// GEMM B (fp16x1): C = Af[M,K] x Wf[N,K]^T, W pre-scaled by 64. 1 MMA pass.
// MODE 0: V projection (scatter fp32 to g_v, scale 1/64). MODE 1: out-proj.
// ===========================================================================
#define STGF (2 * MAT)             // 20480
#define GF_SMEM_BYTES (2 * STGF)   // 40960

template <int MODE>
__global__ __launch_bounds__(256, 2)
void gemm_f16x1_kernel(const __half* __restrict__ Af,
                       const __half* __restrict__ Wf,
                       float* __restrict__ yout)
{
    extern __shared__ char sm[];
    const uint32_t sb = smem_u32(sm);
    const int tid  = threadIdx.x;
    const int wid  = tid >> 5;
    const int lane = tid & 31;
    const int m0   = blockIdx.y * 128;
    const int n0   = blockIdx.x * 128;

    float* out = (MODE == 0) ? g_v : yout;

    const int crow  = tid >> 1;
    const int chalf = tid & 1;
    const size_t aoff = (size_t)(m0 + crow) * KDIM + chalf * 16;
    const size_t boff = (size_t)(n0 + crow) * KDIM + chalf * 16;
    const uint32_t sto = (uint32_t)(crow * ROWB + chalf * 32);

    auto issue = [&](int kc, int buf) {
        const uint32_t st = sb + buf * STGF + sto;
        const size_t ko = (size_t)kc * KC;
        CP16(st,            Af + aoff + ko);
        CP16(st + 16,       Af + aoff + ko + 8);
        CP16(st + MAT,      Wf + boff + ko);
        CP16(st + MAT + 16, Wf + boff + ko + 8);
        CP_COMMIT();
    };

    const int wm = wid & 3;
    const int wn = wid >> 2;
    const int r   = lane & 7;
    const int sel = lane >> 3;
    const uint32_t aBase = (uint32_t)((wm * 32 + r + (sel & 1) * 8) * ROWB +
                                      (sel >> 1) * 16);
    const uint32_t bBase = (uint32_t)((wn * 64 + r + (sel >> 1) * 8) * ROWB +
                                      (sel & 1) * 16);

    float acc[2][8][4];
#pragma unroll
    for (int i = 0; i < 2; i++)
#pragma unroll
        for (int j = 0; j < 8; j++)
#pragma unroll
            for (int t = 0; t < 4; t++) acc[i][j][t] = 0.f;

    issue(0, 0);
    for (int kc = 0; kc < NKC; ++kc) {
        const int cur = kc & 1;
        if (kc + 1 < NKC) { issue(kc + 1, cur ^ 1); CP_WAIT1(); }
        else              { CP_WAIT0(); }
        __syncthreads();

        const uint32_t stage = sb + cur * STGF;
#pragma unroll
        for (int ks = 0; ks < 2; ++ks) {
            const uint32_t koff = ks * 32;
            uint32_t ah[2][4];
#pragma unroll
            for (int i = 0; i < 2; ++i)
                ldsm4(stage + aBase + i * (16 * ROWB) + koff, ah[i]);
#pragma unroll
            for (int j = 0; j < 4; ++j) {
                const uint32_t bA = stage + MAT + bBase + j * (16 * ROWB) + koff;
                uint32_t bh[4];
                ldsm4(bA, bh);
                mma16816h(acc[0][j * 2 + 0], ah[0], bh[0], bh[1]);
                mma16816h(acc[0][j * 2 + 1], ah[0], bh[2], bh[3]);
                mma16816h(acc[1][j * 2 + 0], ah[1], bh[0], bh[1]);
                mma16816h(acc[1][j * 2 + 1], ah[1], bh[2], bh[3]);
            }
        }
        __syncthreads();
    }

#pragma unroll
    for (int i = 0; i < 2; ++i) {
        const int mrow = m0 + wm * 32 + i * 16 + (lane >> 2);
#pragma unroll
        for (int j = 0; j < 8; ++j) {
            const int ncol = n0 + wn * 64 + j * 8 + 2 * (lane & 3);
            if (MODE == 0) {
                const int b = mrow >> 11;
                const int t = mrow & 2047;
                const int h = ncol >> 7;
                const int d = ncol & 127;
                float* dst = &out[(((size_t)(b * NH + h)) * TSEQ + t) * HD + d];
                *(float2*)dst = make_float2(acc[i][j][0] * INV_WSCALE,
                                            acc[i][j][1] * INV_WSCALE);
                *(float2*)(dst + (size_t)8 * HD) =
                    make_float2(acc[i][j][2] * INV_WSCALE,
                                acc[i][j][3] * INV_WSCALE);
            } else {
                // y carries the *64 scale; row L2-norm cancels it exactly.
                float* dst = &out[(size_t)mrow * DIM + ncol];
                *(float2*)dst = make_float2(acc[i][j][0], acc[i][j][1]);
                *(float2*)(dst + (size_t)8 * DIM) =
                    make_float2(acc[i][j][2], acc[i][j][3]);
            }
        }
    }
}

// ---------------------------------------------------------------------------
// Kernel 2: RoPE (table-driven) + sqk*RESTORE (+ATTN_SCALE on q);
// q/k -> bf16 pairs, v -> fp16 single.  256 threads = 4 rows per block.
// ---------------------------------------------------------------------------
__global__ void rope_kernel(const float* __restrict__ sqk)
{
    const int row = blockIdx.x * 4 + (threadIdx.x >> 6);
    const int j   = threadIdx.x & 63;
    const int bh  = row >> 11;
    const int t   = row & 2047;
    const int h   = bh & (NH - 1);
    const size_t base = (size_t)row * HD;

    const float c = g_rc[t * 64 + j];
    const float s = g_rs[t * 64 + j];

    const float s1 = sqk[h * HD + j]      * RESTORE_SCALE;
    const float s2 = sqk[h * HD + 64 + j] * RESTORE_SCALE;

    float qr = g_q[base + j], qi = g_q[base + 64 + j];
    float q1 = (qr * c - qi * s) * s1 * ATTN_SCALE;
    float q2 = (qr * s + qi * c) * s2 * ATTN_SCALE;
    g_qh[base + j]      = __float2bfloat16_rn(q1);
    g_ql[base + j]      = __float2bfloat16_rn(bf_res(q1));
    g_qh[base + 64 + j] = __float2bfloat16_rn(q2);
    g_ql[base + 64 + j] = __float2bfloat16_rn(bf_res(q2));

    float kr = g_k[base + j], ki = g_k[base + 64 + j];
    float k1 = (kr * c - ki * s) * s1;
    float k2 = (kr * s + ki * c) * s2;
    g_kh[base + j]      = __float2bfloat16_rn(k1);
    g_kl[base + j]      = __float2bfloat16_rn(bf_res(k1));
    g_kh[base + 64 + j] = __float2bfloat16_rn(k2);
    g_kl[base + 64 + j] = __float2bfloat16_rn(bf_res(k2));

    g_vf[base + j]      = __float2half_rn(g_v[base + j]);
    g_vf[base + 64 + j] = __float2half_rn(g_v[base + 64 + j]);
}

// ===========================================================================
// Kernel 3: causal flash attention. BR=64 (4 warps), BC=32, double-buffered,
// 128 threads, 2 CTAs/SM.  QK^T bf16x3; PV fp16 single pass.
// ===========================================================================
#define FB_ROWB 272                      // 128 elems * 2B + 16B pad
#define F_QH 0
#define F_QL 17408                       // 64*272
#define F_KV 34816
#define F_KVSTG 26112                    // per stage: Kh,Kl,Vf @ 8704 each
#define F_SMEM_BYTES (F_KV + 2 * F_KVSTG)   // 87,040

__global__ __launch_bounds__(128, 2)
void flash_hmma_kernel()
{
    extern __shared__ char sm[];
    const uint32_t sb = smem_u32(sm);
    const int tid  = threadIdx.x;
    const int w    = tid >> 5;
    const int lane = tid & 31;
    const int i0   = (int)(gridDim.x - 1 - blockIdx.x) * 64;
    const int bh   = blockIdx.y;
    const int b    = bh >> 4;
    const int h    = bh & 15;
    const size_t kvbase = (size_t)bh * TSEQ * HD;

    // ---- prologue: Q (hi+lo) and KV tile 0 ----
    {
        const size_t qgbase = kvbase + (size_t)i0 * HD;
#pragma unroll
        for (int it = 0; it < 16; ++it) {
            const int idx = (it & 7) * 128 + tid;
            const int row = idx >> 4;
            const int ch  = idx & 15;
            const uint32_t dst = sb + ((it < 8) ? F_QH : F_QL) +
                                 row * FB_ROWB + ch * 16;
            const __nv_bfloat16* src = (it < 8) ? g_qh : g_ql;
            CP16(dst, src + qgbase + (size_t)row * HD + ch * 8);
        }
#pragma unroll
        for (int it = 0; it < 12; ++it) {
            const int mat = it >> 2;                  // 0:Kh 1:Kl 2:Vf
            const int idx = (it & 3) * 128 + tid;     // 0..511
            const int row = idx >> 4;
            const int ch  = idx & 15;
            const uint32_t dst = sb + F_KV + mat * 8704 +
                                 row * FB_ROWB + ch * 16;
            const void* src =
                (mat == 0) ? (const void*)(g_kh + kvbase + (size_t)row * HD + ch * 8)
              : (mat == 1) ? (const void*)(g_kl + kvbase + (size_t)row * HD + ch * 8)
                           : (const void*)(g_vf + kvbase + (size_t)row * HD + ch * 8);
            CP16(dst, src);
        }
        CP_COMMIT();
    }

    const int r   = lane & 7;
    const int sel = lane >> 3;
    const uint32_t qBase = (uint32_t)((w * 16 + r + (sel & 1) * 8) * FB_ROWB +
                                      (sel >> 1) * 16);
    const uint32_t kBase = (uint32_t)((r + (sel >> 1) * 8) * FB_ROWB +
                                      (sel & 1) * 16);
    const uint32_t vBase = (uint32_t)(((sel & 1) * 8 + r) * FB_ROWB +
                                      (sel >> 1) * 16);

    float o[16][4];
#pragma unroll
    for (int i = 0; i < 16; i++)
#pragma unroll
        for (int t = 0; t < 4; t++) o[i][t] = 0.f;
    float m1 = -1e30f, m2 = -1e30f, l1 = 0.f, l2 = 0.f;
    const int grow1 = i0 + w * 16 + (lane >> 2);
    const int grow2 = grow1 + 8;

    const int ntiles = (i0 >> 5) + 2;
    for (int jt = 0; jt < ntiles; ++jt) {
        const int j0 = jt * 32;
        if (jt + 1 < ntiles) {
            const int nj0 = j0 + 32;
            const uint32_t stg = sb + F_KV + ((jt + 1) & 1) * F_KVSTG;
#pragma unroll
            for (int it = 0; it < 12; ++it) {
                const int mat = it >> 2;
                const int idx = (it & 3) * 128 + tid;
                const int row = idx >> 4;
                const int ch  = idx & 15;
                const uint32_t dst = stg + mat * 8704 + row * FB_ROWB + ch * 16;
                const void* src =
                    (mat == 0) ? (const void*)(g_kh + kvbase + (size_t)(nj0 + row) * HD + ch * 8)
                  : (mat == 1) ? (const void*)(g_kl + kvbase + (size_t)(nj0 + row) * HD + ch * 8)
                               : (const void*)(g_vf + kvbase + (size_t)(nj0 + row) * HD + ch * 8);
                CP16(dst, src);
            }
            CP_COMMIT();
            CP_WAIT1();
        } else {
            CP_WAIT0();
        }
        __syncthreads();

        const uint32_t stg = sb + F_KV + (jt & 1) * F_KVSTG;
        const uint32_t KH = stg, KL = stg + 8704, VF = stg + 17408;

        // ---- S = Q K^T (bf16x3), per warp 16x32 ----
        float s[4][4];
#pragma unroll
        for (int i = 0; i < 4; i++)
#pragma unroll
            for (int t = 0; t < 4; t++) s[i][t] = 0.f;

#pragma unroll
        for (int kk = 0; kk < 8; ++kk) {
            uint32_t ah[4], al[4];
            ldsm4(sb + F_QH + qBase + kk * 32, ah);
            ldsm4(sb + F_QL + qBase + kk * 32, al);
#pragma unroll
            for (int j = 0; j < 2; ++j) {
                const uint32_t kA = kBase + j * (16 * FB_ROWB) + kk * 32;
                uint32_t bhf[4], blf[4];
                ldsm4(KH + kA, bhf);
                ldsm4(KL + kA, blf);
                mma16816(s[j * 2 + 0], ah, bhf[0], bhf[1]);
                mma16816(s[j * 2 + 1], ah, bhf[2], bhf[3]);
                mma16816(s[j * 2 + 0], ah, blf[0], blf[1]);
                mma16816(s[j * 2 + 1], ah, blf[2], blf[3]);
                mma16816(s[j * 2 + 0], al, bhf[0], bhf[1]);
                mma16816(s[j * 2 + 1], al, bhf[2], bhf[3]);
            }
        }

        // ---- causal mask ----
        if (j0 + 31 > i0 + w * 16) {
#pragma unroll
            for (int t8 = 0; t8 < 4; ++t8) {
                const int gcol = j0 + t8 * 8 + 2 * (lane & 3);
                if (gcol > grow1)     s[t8][0] = -1e30f;
                if (gcol + 1 > grow1) s[t8][1] = -1e30f;
                if (gcol > grow2)     s[t8][2] = -1e30f;
                if (gcol + 1 > grow2) s[t8][3] = -1e30f;
            }
        }

        // ---- online softmax ----
        float nm1 = m1, nm2 = m2;
#pragma unroll
        for (int t8 = 0; t8 < 4; ++t8) {
            nm1 = fmaxf(nm1, fmaxf(s[t8][0], s[t8][1]));
            nm2 = fmaxf(nm2, fmaxf(s[t8][2], s[t8][3]));
        }
        nm1 = fmaxf(nm1, __shfl_xor_sync(0xffffffffu, nm1, 1));
        nm1 = fmaxf(nm1, __shfl_xor_sync(0xffffffffu, nm1, 2));
        nm2 = fmaxf(nm2, __shfl_xor_sync(0xffffffffu, nm2, 1));
        nm2 = fmaxf(nm2, __shfl_xor_sync(0xffffffffu, nm2, 2));
        const float a1 = __expf(m1 - nm1);
        const float a2 = __expf(m2 - nm2);
        float r1 = 0.f, r2 = 0.f;
#pragma unroll
        for (int t8 = 0; t8 < 4; ++t8) {
            s[t8][0] = __expf(s[t8][0] - nm1);
            s[t8][1] = __expf(s[t8][1] - nm1);
            s[t8][2] = __expf(s[t8][2] - nm2);
            s[t8][3] = __expf(s[t8][3] - nm2);
            r1 += s[t8][0] + s[t8][1];
            r2 += s[t8][2] + s[t8][3];
        }
        r1 += __shfl_xor_sync(0xffffffffu, r1, 1);
        r1 += __shfl_xor_sync(0xffffffffu, r1, 2);
        r2 += __shfl_xor_sync(0xffffffffu, r2, 1);
        r2 += __shfl_xor_sync(0xffffffffu, r2, 2);
        l1 = l1 * a1 + r1;
        l2 = l2 * a2 + r2;
        m1 = nm1; m2 = nm2;
#pragma unroll
        for (int i = 0; i < 16; ++i) {
            o[i][0] *= a1; o[i][1] *= a1;
            o[i][2] *= a2; o[i][3] *= a2;
        }

        // ---- O += Ph Vf, fp16, single pass ----
#pragma unroll
        for (int kk = 0; kk < 2; ++kk) {
            uint32_t pah[4];
            {
                const float* p0 = s[2 * kk];
                const float* p1 = s[2 * kk + 1];
                pah[0] = pack2h(p0[0], p0[1]);
                pah[1] = pack2h(p0[2], p0[3]);
                pah[2] = pack2h(p1[0], p1[1]);
                pah[3] = pack2h(p1[2], p1[3]);
            }
#pragma unroll
            for (int dc = 0; dc < 4; ++dc) {
                uint32_t vh[2][4];
#pragma unroll
                for (int u = 0; u < 2; ++u) {
                    const uint32_t vA = vBase + kk * (16 * FB_ROWB) +
                                        (dc * 2 + u) * 32;
                    ldsm4t(VF + vA, vh[u]);
                }
#pragma unroll
                for (int u = 0; u < 2; ++u) {
                    mma16816h(o[(dc * 2 + u) * 2 + 0], pah, vh[u][0], vh[u][1]);
                    mma16816h(o[(dc * 2 + u) * 2 + 1], pah, vh[u][2], vh[u][3]);
                }
            }
        }
        __syncthreads();
    }

    // ---- epilogue: att as fp16 single ----
    const float inv1 = 1.0f / l1;
    const float inv2 = 1.0f / l2;
#pragma unroll
    for (int ot = 0; ot < 16; ++ot) {
        const int cold = ot * 8 + 2 * (lane & 3);
        const size_t i1 = ((size_t)(b * TSEQ + grow1)) * DIM + h * HD + cold;
        const size_t i2 = ((size_t)(b * TSEQ + grow2)) * DIM + h * HD + cold;
        *(uint32_t*)&g_af[i1] = pack2h(o[ot][0] * inv1, o[ot][1] * inv1);
        *(uint32_t*)&g_af[i2] = pack2h(o[ot][2] * inv2, o[ot][3] * inv2);
    }
}

// ---------------------------------------------------------------------------
// Kernel 5: per-row L2 normalization of y (in place on d_out)
// ---------------------------------------------------------------------------
__global__ void norm_kernel(float* __restrict__ y)
{
    const int row = blockIdx.x;
    float4* p = (float4*)(y + (size_t)row * DIM);
    float ss = 0.f;
#pragma unroll
    for (int i = threadIdx.x; i < DIM / 4; i += 256) {
        float4 v = p[i];
        ss += v.x * v.x + v.y * v.y + v.z * v.z + v.w * v.w;
    }
    ss += __shfl_xor_sync(0xffffffffu, ss, 16);
    ss += __shfl_xor_sync(0xffffffffu, ss, 8);
    ss += __shfl_xor_sync(0xffffffffu, ss, 4);
    ss += __shfl_xor_sync(0xffffffffu, ss, 2);
    ss += __shfl_xor_sync(0xffffffffu, ss, 1);
    __shared__ float red[8];
    if ((threadIdx.x & 31) == 0) red[threadIdx.x >> 5] = ss;
    __syncthreads();
    float tot = red[0] + red[1] + red[2] + red[3] +
                red[4] + red[5] + red[6] + red[7];
    const float inv = 1.0f / fmaxf(sqrtf(tot), 1e-12f);
#pragma unroll
    for (int i = threadIdx.x; i < DIM / 4; i += 256) {
        float4 v = p[i];
        v.x *= inv; v.y *= inv; v.z *= inv; v.w *= inv;
        p[i] = v;
    }
}

// ---------------------------------------------------------------------------
// Launch
// ---------------------------------------------------------------------------
extern "C" void kernel_launch(void* const* d_in, const int* in_sizes, int n_in,
                              void* d_out, int out_size)
{
    const float* x   = (const float*)d_in[0];
    const float* Wq  = (const float*)d_in[1];
    const float* Wk  = (const float*)d_in[2];
    const float* Wv  = (const float*)d_in[3];
    const float* Wo  = (const float*)d_in[4];
    const float* sqk = (const float*)d_in[5];
    float* y = (float*)d_out;

    __nv_bfloat16 *xh, *xl, *wqh, *wql, *wkh, *wkl;
    __half *xf, *wvf, *wof, *af;
    cudaGetSymbolAddress((void**)&xh,  g_xh);
    cudaGetSymbolAddress((void**)&xl,  g_xl);
    cudaGetSymbolAddress((void**)&wqh, g_wqh);
    cudaGetSymbolAddress((void**)&wql, g_wql);
    cudaGetSymbolAddress((void**)&wkh, g_wkh);
    cudaGetSymbolAddress((void**)&wkl, g_wkl);
    cudaGetSymbolAddress((void**)&xf,  g_xf);
    cudaGetSymbolAddress((void**)&wvf, g_wvf);
    cudaGetSymbolAddress((void**)&wof, g_wof);
    cudaGetSymbolAddress((void**)&af,  g_af);

    cudaFuncSetAttribute(flash_hmma_kernel,
                         cudaFuncAttributeMaxDynamicSharedMemorySize,
                         F_SMEM_BYTES);
    cudaFuncSetAttribute(gemm_bf16x3_kernel,
                         cudaFuncAttributeMaxDynamicSharedMemorySize,
                         G_SMEM_BYTES);
    cudaFuncSetAttribute(gemm_f16x1_kernel<0>,
                         cudaFuncAttributeMaxDynamicSharedMemorySize,
                         GF_SMEM_BYTES);
    cudaFuncSetAttribute(gemm_f16x1_kernel<1>,
                         cudaFuncAttributeMaxDynamicSharedMemorySize,
                         GF_SMEM_BYTES);

    rope_table_kernel<<<TSEQ, 64>>>();

    const int NX4 = MROWS * DIM / 4;   // largest convert
    convert_all_kernel<<<dim3((NX4 + 255) / 256, 6), 256>>>(x, Wq, Wk, Wv, Wo);

    gemm_bf16x3_kernel<<<dim3(DIM / 128, MROWS / 128, 2), 256, G_SMEM_BYTES>>>(
        xh, xl, wqh, wql, wkh, wkl);
    gemm_f16x1_kernel<0><<<dim3(DIM / 128, MROWS / 128), 256, GF_SMEM_BYTES>>>(
        xf, wvf, nullptr);
    rope_kernel<<<BATCH * NH * TSEQ / 4, 256>>>(sqk);
    flash_hmma_kernel<<<dim3(TSEQ / 64, BATCH * NH), 128, F_SMEM_BYTES>>>();
    gemm_f16x1_kernel<1><<<dim3(DIM / 128, MROWS / 128), 256, GF_SMEM_BYTES>>>(
        af, wof, y);
    norm_kernel<<<MROWS, 256>>>(y);
}

// round 16
// speedup vs baseline: 1.2661x; 1.0378x over previous
#include <cuda_runtime.h>
#include <cuda_bf16.h>
#include <cuda_fp16.h>
#include <math.h>
#include <stdint.h>

// Problem constants
#define BATCH 2
#define TSEQ  2048
#define DIM   2048
#define NH    16
#define HD    128
#define MROWS (BATCH * TSEQ)      // 4096
#define KDIM  DIM                 // 2048
#define NELEM ((size_t)BATCH * NH * TSEQ * HD)   // 8.4M

#define RESTORE_SCALE 45.25483399593904f   // sqrt(2048)
#define ATTN_SCALE    11.313708498984761f  // sqrt(128)
#define WSCALE 64.0f
#define INV_WSCALE (1.0f / 64.0f)

// ---------------------------------------------------------------------------
// Scratch (device globals — allocation-free rule)
// ---------------------------------------------------------------------------
__device__ float g_q[NELEM];                 // [B,H,T,HD] fp32 (pre-rope)
__device__ float g_k[NELEM];
__device__ float g_v[NELEM];

// bf16 pairs (high-precision Q/K path)
__device__ __nv_bfloat16 g_xh[(size_t)MROWS * DIM], g_xl[(size_t)MROWS * DIM];
__device__ __nv_bfloat16 g_wqh[(size_t)DIM * DIM], g_wql[(size_t)DIM * DIM];
__device__ __nv_bfloat16 g_wkh[(size_t)DIM * DIM], g_wkl[(size_t)DIM * DIM];
__device__ __nv_bfloat16 g_qh[NELEM], g_ql[NELEM];   // roped+scaled q
__device__ __nv_bfloat16 g_kh[NELEM], g_kl[NELEM];   // roped+scaled k

// fp16 single path (V / att / out-proj)
__device__ __half g_xf[(size_t)MROWS * DIM];                 // x fp16
__device__ __half g_wvf[(size_t)DIM * DIM];                  // Wv*64 fp16
__device__ __half g_wof[(size_t)DIM * DIM];                  // Wo*64 fp16
__device__ __half g_vf[NELEM];                               // v fp16
__device__ __half g_af[(size_t)MROWS * DIM];                 // attn out fp16

// RoPE tables: cos/sin for (t, j), t in [0,2048), j in [0,64)
__device__ float g_rc[TSEQ * 64];
__device__ float g_rs[TSEQ * 64];

// ---------------------------------------------------------------------------
// PTX helpers (base sm_103 target safe: ldmatrix / mma.sync / cp.async)
// ---------------------------------------------------------------------------
__device__ __forceinline__ uint32_t smem_u32(const void* p) {
    uint32_t a;
    asm("{ .reg .u64 t; cvta.to.shared.u64 t, %1; cvt.u32.u64 %0, t; }"
        : "=r"(a) : "l"(p));
    return a;
}
__device__ __forceinline__ void ldsm4(uint32_t addr, uint32_t r[4]) {
    asm volatile("ldmatrix.sync.aligned.m8n8.x4.shared.b16 {%0,%1,%2,%3}, [%4];"
        : "=r"(r[0]), "=r"(r[1]), "=r"(r[2]), "=r"(r[3]) : "r"(addr));
}
__device__ __forceinline__ void ldsm4t(uint32_t addr, uint32_t r[4]) {
    asm volatile("ldmatrix.sync.aligned.m8n8.x4.trans.shared.b16 {%0,%1,%2,%3}, [%4];"
        : "=r"(r[0]), "=r"(r[1]), "=r"(r[2]), "=r"(r[3]) : "r"(addr));
}
__device__ __forceinline__ void mma16816(float c[4], const uint32_t a[4],
                                         uint32_t b0, uint32_t b1) {
    asm volatile(
        "mma.sync.aligned.m16n8k16.row.col.f32.bf16.bf16.f32 "
        "{%0,%1,%2,%3}, {%4,%5,%6,%7}, {%8,%9}, {%0,%1,%2,%3};"
        : "+f"(c[0]), "+f"(c[1]), "+f"(c[2]), "+f"(c[3])
        : "r"(a[0]), "r"(a[1]), "r"(a[2]), "r"(a[3]), "r"(b0), "r"(b1));
}
__device__ __forceinline__ void mma16816h(float c[4], const uint32_t a[4],
                                          uint32_t b0, uint32_t b1) {
    asm volatile(
        "mma.sync.aligned.m16n8k16.row.col.f32.f16.f16.f32 "
        "{%0,%1,%2,%3}, {%4,%5,%6,%7}, {%8,%9}, {%0,%1,%2,%3};"
        : "+f"(c[0]), "+f"(c[1]), "+f"(c[2]), "+f"(c[3])
        : "r"(a[0]), "r"(a[1]), "r"(a[2]), "r"(a[3]), "r"(b0), "r"(b1));
}
#define CP16(dst, src) \
    asm volatile("cp.async.cg.shared.global [%0], [%1], 16;" \
        :: "r"(dst), "l"(src))
#define CP_COMMIT() asm volatile("cp.async.commit_group;" ::: "memory")
#define CP_WAIT1()  asm volatile("cp.async.wait_group 1;" ::: "memory")
#define CP_WAIT0()  asm volatile("cp.async.wait_group 0;" ::: "memory")

__device__ __forceinline__ uint32_t pack2bf(float x, float y) {
    __nv_bfloat162 t = __floats2bfloat162_rn(x, y);
    return *(uint32_t*)&t;
}
__device__ __forceinline__ float bf_res(float x) {       // x - bf16(x)
    return x - __bfloat162float(__float2bfloat16_rn(x));
}
__device__ __forceinline__ uint32_t pack2h(float x, float y) {
    __half2 t = __floats2half2_rn(x, y);
    return *(uint32_t*)&t;
}

// ---------------------------------------------------------------------------
// Kernel -1: RoPE table build. fp64 once per (t,j).
// ---------------------------------------------------------------------------
__global__ void rope_table_kernel()
{
    const int t = blockIdx.x;
    const int j = threadIdx.x;
    const double theta = exp(-(double)j * (9.210340371976184 / 64.0));
    double sd, cd;
    sincos((double)t * theta, &sd, &cd);
    g_rc[t * 64 + j] = (float)cd;
    g_rs[t * 64 + j] = (float)sd;
}

// ---------------------------------------------------------------------------
// Kernel 0: fused converters.
// y=0: x -> bf16 pair AND fp16 single (one read of x)
// y=1: Wq, y=2: Wk (bf16 pairs); y=3: Wv*64 fp16; y=4: Wo*64 fp16
// ---------------------------------------------------------------------------
__global__ void convert_all_kernel(const float* __restrict__ x,
                                   const float* __restrict__ Wq,
                                   const float* __restrict__ Wk,
                                   const float* __restrict__ Wv,
                                   const float* __restrict__ Wo)
{
    const int i = blockIdx.x * 256 + threadIdx.x;
    const int kind = blockIdx.y;
    if (kind == 0) {
        const int n4 = MROWS * DIM / 4;
        if (i >= n4) return;
        float4 v = ((const float4*)x)[i];
        ((uint2*)g_xh)[i] = make_uint2(pack2bf(v.x, v.y), pack2bf(v.z, v.w));
        ((uint2*)g_xl)[i] = make_uint2(pack2bf(bf_res(v.x), bf_res(v.y)),
                                       pack2bf(bf_res(v.z), bf_res(v.w)));
        ((uint2*)g_xf)[i] = make_uint2(pack2h(v.x, v.y), pack2h(v.z, v.w));
    } else if (kind <= 2) {
        const float* src; __nv_bfloat16* hi; __nv_bfloat16* lo;
        if (kind == 1) { src = Wq; hi = g_wqh; lo = g_wql; }
        else           { src = Wk; hi = g_wkh; lo = g_wkl; }
        const int n4 = DIM * DIM / 4;
        if (i >= n4) return;
        float4 v = ((const float4*)src)[i];
        ((uint2*)hi)[i] = make_uint2(pack2bf(v.x, v.y), pack2bf(v.z, v.w));
        ((uint2*)lo)[i] = make_uint2(pack2bf(bf_res(v.x), bf_res(v.y)),
                                     pack2bf(bf_res(v.z), bf_res(v.w)));
    } else {
        const float* src; __half* dst;
        if (kind == 3) { src = Wv; dst = g_wvf; }
        else           { src = Wo; dst = g_wof; }
        const int n4 = DIM * DIM / 4;
        if (i >= n4) return;
        float4 v = ((const float4*)src)[i];
        ((uint2*)dst)[i] = make_uint2(pack2h(v.x * WSCALE, v.y * WSCALE),
                                      pack2h(v.z * WSCALE, v.w * WSCALE));
    }
}

// ===========================================================================
// Tiling constants (identical to R15 for both paths)
// ===========================================================================
#define KC 32
#define NKC (KDIM / KC)            // 64
#define ROWB 80
#define MAT 10240                  // 128*80
#define STG (4 * MAT)              // 40960  (bf16x3 path: 4 matrices)
#define STGF (2 * MAT)             // 20480  (f16x1 path: 2 matrices)
#define G_SMEM_BYTES (2 * STG)     // 81920  (covers both paths)
#define GF_SMEM_BYTES (2 * STGF)   // 40960

// ===========================================================================
// Merged projection kernel. grid = (16, 32, 3); z-major order puts V last
// so its CTAs backfill the QK tail wave.
// z in {0,1}: Q/K via bf16x3 (exact R15 body, fp32 out to g_q/g_k).
// z == 2:    V via fp16x1 (exact R15 body, fp32 scatter to g_v).
// ===========================================================================
__global__ __launch_bounds__(256, 2)
void proj_kernel(const __nv_bfloat16* __restrict__ Ah,
                 const __nv_bfloat16* __restrict__ Al,
                 const __nv_bfloat16* __restrict__ Wqh,
                 const __nv_bfloat16* __restrict__ Wql,
                 const __nv_bfloat16* __restrict__ Wkh,
                 const __nv_bfloat16* __restrict__ Wkl,
                 const __half* __restrict__ xf,
                 const __half* __restrict__ wvf)
{
    extern __shared__ char sm[];
    const uint32_t sb = smem_u32(sm);
    const int tid  = threadIdx.x;
    const int wid  = tid >> 5;
    const int lane = tid & 31;
    const int m0   = blockIdx.y * 128;
    const int n0   = blockIdx.x * 128;

    const int wm = wid & 3;
    const int wn = wid >> 2;
    const int r   = lane & 7;
    const int sel = lane >> 3;

    const int crow  = tid >> 1;
    const int chalf = tid & 1;
    const uint32_t sto = (uint32_t)(crow * ROWB + chalf * 32);
    const uint32_t aBase = (uint32_t)((wm * 32 + r + (sel & 1) * 8) * ROWB +
                                      (sel >> 1) * 16);
    const uint32_t bBase = (uint32_t)((wn * 64 + r + (sel >> 1) * 8) * ROWB +
                                      (sel & 1) * 16);

    float acc[2][8][4];
#pragma unroll
    for (int i = 0; i < 2; i++)
#pragma unroll
        for (int j = 0; j < 8; j++)
#pragma unroll
            for (int t = 0; t < 4; t++) acc[i][j][t] = 0.f;

    if (blockIdx.z == 2) {
        // ------------------- V projection (fp16x1, KC=32) -------------------
        const size_t aoff = (size_t)(m0 + crow) * KDIM + chalf * 16;
        const size_t boff = (size_t)(n0 + crow) * KDIM + chalf * 16;

        auto issue = [&](int kc, int buf) {
            const uint32_t st = sb + buf * STGF + sto;
            const size_t ko = (size_t)kc * KC;
            CP16(st,            xf  + aoff + ko);
            CP16(st + 16,       xf  + aoff + ko + 8);
            CP16(st + MAT,      wvf + boff + ko);
            CP16(st + MAT + 16, wvf + boff + ko + 8);
            CP_COMMIT();
        };

        issue(0, 0);
        for (int kc = 0; kc < NKC; ++kc) {
            const int cur = kc & 1;
            if (kc + 1 < NKC) { issue(kc + 1, cur ^ 1); CP_WAIT1(); }
            else              { CP_WAIT0(); }
            __syncthreads();

            const uint32_t stage = sb + cur * STGF;
#pragma unroll
            for (int ks = 0; ks < 2; ++ks) {
                const uint32_t koff = ks * 32;
                uint32_t ah[2][4];
#pragma unroll
                for (int i = 0; i < 2; ++i)
                    ldsm4(stage + aBase + i * (16 * ROWB) + koff, ah[i]);
#pragma unroll
                for (int j = 0; j < 4; ++j) {
                    const uint32_t bA = stage + MAT + bBase +
                                        j * (16 * ROWB) + koff;
                    uint32_t bh[4];
                    ldsm4(bA, bh);
                    mma16816h(acc[0][j * 2 + 0], ah[0], bh[0], bh[1]);
                    mma16816h(acc[0][j * 2 + 1], ah[0], bh[2], bh[3]);
                    mma16816h(acc[1][j * 2 + 0], ah[1], bh[0], bh[1]);
                    mma16816h(acc[1][j * 2 + 1], ah[1], bh[2], bh[3]);
                }
            }
            __syncthreads();
        }

#pragma unroll
        for (int i = 0; i < 2; ++i) {
            const int mrow = m0 + wm * 32 + i * 16 + (lane >> 2);
            const int b = mrow >> 11;
            const int t = mrow & 2047;
#pragma unroll
            for (int j = 0; j < 8; ++j) {
                const int ncol = n0 + wn * 64 + j * 8 + 2 * (lane & 3);
                const int h = ncol >> 7;
                const int d = ncol & 127;
                float* dst = &g_v[(((size_t)(b * NH + h)) * TSEQ + t) * HD + d];
                *(float2*)dst = make_float2(acc[i][j][0] * INV_WSCALE,
                                            acc[i][j][1] * INV_WSCALE);
                *(float2*)(dst + (size_t)8 * HD) =
                    make_float2(acc[i][j][2] * INV_WSCALE,
                                acc[i][j][3] * INV_WSCALE);
            }
        }
        return;
    }

    // ---------------------- Q/K projection (bf16x3) --------------------------
    const __nv_bfloat16* Bh = (blockIdx.z == 0) ? Wqh : Wkh;
    const __nv_bfloat16* Bl = (blockIdx.z == 0) ? Wql : Wkl;
    float* out = (blockIdx.z == 0) ? g_q : g_k;

    const size_t aoff = (size_t)(m0 + crow) * KDIM + chalf * 16;
    const size_t boff = (size_t)(n0 + crow) * KDIM + chalf * 16;

    auto issue = [&](int kc, int buf) {
        const uint32_t st = sb + buf * STG + sto;
        const size_t ko = (size_t)kc * KC;
        CP16(st,                 Ah + aoff + ko);
        CP16(st + 16,            Ah + aoff + ko + 8);
        CP16(st + MAT,           Al + aoff + ko);
        CP16(st + MAT + 16,      Al + aoff + ko + 8);
        CP16(st + 2 * MAT,       Bh + boff + ko);
        CP16(st + 2 * MAT + 16,  Bh + boff + ko + 8);
        CP16(st + 3 * MAT,       Bl + boff + ko);
        CP16(st + 3 * MAT + 16,  Bl + boff + ko + 8);
        CP_COMMIT();
    };

    issue(0, 0);
    for (int kc = 0; kc < NKC; ++kc) {
        const int cur = kc & 1;
        if (kc + 1 < NKC) { issue(kc + 1, cur ^ 1); CP_WAIT1(); }
        else              { CP_WAIT0(); }
        __syncthreads();

        const uint32_t stage = sb + cur * STG;
#pragma unroll
        for (int ks = 0; ks < 2; ++ks) {
            const uint32_t koff = ks * 32;
            uint32_t ah[2][4], al[2][4];
#pragma unroll
            for (int i = 0; i < 2; ++i) {
                const uint32_t aA = stage + aBase + i * (16 * ROWB) + koff;
                ldsm4(aA, ah[i]);
                ldsm4(aA + MAT, al[i]);
            }
#pragma unroll
            for (int j = 0; j < 4; ++j) {
                const uint32_t bA = stage + 2 * MAT + bBase + j * (16 * ROWB) + koff;
                uint32_t bh[4], bl[4];
                ldsm4(bA, bh);
                ldsm4(bA + MAT, bl);
                mma16816(acc[0][j * 2 + 0], ah[0], bh[0], bh[1]);
                mma16816(acc[0][j * 2 + 1], ah[0], bh[2], bh[3]);
                mma16816(acc[1][j * 2 + 0], ah[1], bh[0], bh[1]);
                mma16816(acc[1][j * 2 + 1], ah[1], bh[2], bh[3]);
                mma16816(acc[0][j * 2 + 0], ah[0], bl[0], bl[1]);
                mma16816(acc[0][j * 2 + 1], ah[0], bl[2], bl[3]);
                mma16816(acc[1][j * 2 + 0], ah[1], bl[0], bl[1]);
                mma16816(acc[1][j * 2 + 1], ah[1], bl[2], bl[3]);
                mma16816(acc[0][j * 2 + 0], al[0], bh[0], bh[1]);
                mma16816(acc[0][j * 2 + 1], al[0], bh[2], bh[3]);
                mma16816(acc[1][j * 2 + 0], al[1], bh[0], bh[1]);
                mma16816(acc[1][j * 2 + 1], al[1], bh[2], bh[3]);
            }
        }
        __syncthreads();
    }

    // scatter epilogue to [B,H,T,HD]
#pragma unroll
    for (int i = 0; i < 2; ++i) {
        const int mrow = m0 + wm * 32 + i * 16 + (lane >> 2);
        const int b = mrow >> 11;
        const int t = mrow & 2047;
#pragma unroll
        for (int j = 0; j < 8; ++j) {
            const int ncol = n0 + wn * 64 + j * 8 + 2 * (lane & 3);
            const int h = ncol >> 7;
            const int d = ncol & 127;
            float* dst = &out[(((size_t)(b * NH + h)) * TSEQ + t) * HD + d];
            *(float2*)dst = make_float2(acc[i][j][0], acc[i][j][1]);
            *(float2*)(dst + (size_t)8 * HD) =
                make_float2(acc[i][j][2], acc[i][j][3]);
        }
    }
}

// ===========================================================================
// Output projection: y = att @ (Wo*64)^T  (fp16x1, KC=32).
// y carries *64 scale; row L2-norm cancels it exactly.
// ===========================================================================
__global__ __launch_bounds__(256, 2)
void out_proj_kernel(const __half* __restrict__ Af,
                     const __half* __restrict__ Wf,
                     float* __restrict__ yout)
{
    extern __shared__ char sm[];
    const uint32_t sb = smem_u32(sm);
    const int tid  = threadIdx.x;
    const int wid  = tid >> 5;
    const int lane = tid & 31;
    const int m0   = blockIdx.y * 128;
    const int n0   = blockIdx.x * 128;

    const int crow  = tid >> 1;
    const int chalf = tid & 1;
    const size_t aoff = (size_t)(m0 + crow) * KDIM + chalf * 16;
    const size_t boff = (size_t)(n0 + crow) * KDIM + chalf * 16;
    const uint32_t sto = (uint32_t)(crow * ROWB + chalf * 32);

    auto issue = [&](int kc, int buf) {
        const uint32_t st = sb + buf * STGF + sto;
        const size_t ko = (size_t)kc * KC;
        CP16(st,            Af + aoff + ko);
        CP16(st + 16,       Af + aoff + ko + 8);
        CP16(st + MAT,      Wf + boff + ko);
        CP16(st + MAT + 16, Wf + boff + ko + 8);
        CP_COMMIT();
    };

    const int wm = wid & 3;
    const int wn = wid >> 2;
    const int r   = lane & 7;
    const int sel = lane >> 3;
    const uint32_t aBase = (uint32_t)((wm * 32 + r + (sel & 1) * 8) * ROWB +
                                      (sel >> 1) * 16);
    const uint32_t bBase = (uint32_t)((wn * 64 + r + (sel >> 1) * 8) * ROWB +
                                      (sel & 1) * 16);

    float acc[2][8][4];
#pragma unroll
    for (int i = 0; i < 2; i++)
#pragma unroll
        for (int j = 0; j < 8; j++)
#pragma unroll
            for (int t = 0; t < 4; t++) acc[i][j][t] = 0.f;

    issue(0, 0);
    for (int kc = 0; kc < NKC; ++kc) {
        const int cur = kc & 1;
        if (kc + 1 < NKC) { issue(kc + 1, cur ^ 1); CP_WAIT1(); }
        else              { CP_WAIT0(); }
        __syncthreads();

        const uint32_t stage = sb + cur * STGF;
#pragma unroll
        for (int ks = 0; ks < 2; ++ks) {
            const uint32_t koff = ks * 32;
            uint32_t ah[2][4];
#pragma unroll
            for (int i = 0; i < 2; ++i)
                ldsm4(stage + aBase + i * (16 * ROWB) + koff, ah[i]);
#pragma unroll
            for (int j = 0; j < 4; ++j) {
                const uint32_t bA = stage + MAT + bBase + j * (16 * ROWB) + koff;
                uint32_t bh[4];
                ldsm4(bA, bh);
                mma16816h(acc[0][j * 2 + 0], ah[0], bh[0], bh[1]);
                mma16816h(acc[0][j * 2 + 1], ah[0], bh[2], bh[3]);
                mma16816h(acc[1][j * 2 + 0], ah[1], bh[0], bh[1]);
                mma16816h(acc[1][j * 2 + 1], ah[1], bh[2], bh[3]);
            }
        }
        __syncthreads();
    }

#pragma unroll
    for (int i = 0; i < 2; ++i) {
        const int mrow = m0 + wm * 32 + i * 16 + (lane >> 2);
#pragma unroll
        for (int j = 0; j < 8; ++j) {
            const int ncol = n0 + wn * 64 + j * 8 + 2 * (lane & 3);
            float* dst = &yout[(size_t)mrow * DIM + ncol];
            *(float2*)dst = make_float2(acc[i][j][0], acc[i][j][1]);
            *(float2*)(dst + (size_t)8 * DIM) =
                make_float2(acc[i][j][2], acc[i][j][3]);
        }
    }
}

// ---------------------------------------------------------------------------
// Kernel 2: RoPE (table-driven) + sqk*RESTORE (+ATTN_SCALE on q);
// q/k -> bf16 pairs, v -> fp16 single.  256 threads = 4 rows per block.
// ---------------------------------------------------------------------------
__global__ void rope_kernel(const float* __restrict__ sqk)
{
    const int row = blockIdx.x * 4 + (threadIdx.x >> 6);
    const int j   = threadIdx.x & 63;
    const int bh  = row >> 11;
    const int t   = row & 2047;
    const int h   = bh & (NH - 1);
    const size_t base = (size_t)row * HD;

    const float c = g_rc[t * 64 + j];
    const float s = g_rs[t * 64 + j];

    const float s1 = sqk[h * HD + j]      * RESTORE_SCALE;
    const float s2 = sqk[h * HD + 64 + j] * RESTORE_SCALE;

    float qr = g_q[base + j], qi = g_q[base + 64 + j];
    float q1 = (qr * c - qi * s) * s1 * ATTN_SCALE;
    float q2 = (qr * s + qi * c) * s2 * ATTN_SCALE;
    g_qh[base + j]      = __float2bfloat16_rn(q1);
    g_ql[base + j]      = __float2bfloat16_rn(bf_res(q1));
    g_qh[base + 64 + j] = __float2bfloat16_rn(q2);
    g_ql[base + 64 + j] = __float2bfloat16_rn(bf_res(q2));

    float kr = g_k[base + j], ki = g_k[base + 64 + j];
    float k1 = (kr * c - ki * s) * s1;
    float k2 = (kr * s + ki * c) * s2;
    g_kh[base + j]      = __float2bfloat16_rn(k1);
    g_kl[base + j]      = __float2bfloat16_rn(bf_res(k1));
    g_kh[base + 64 + j] = __float2bfloat16_rn(k2);
    g_kl[base + 64 + j] = __float2bfloat16_rn(bf_res(k2));

    g_vf[base + j]      = __float2half_rn(g_v[base + j]);
    g_vf[base + 64 + j] = __float2half_rn(g_v[base + 64 + j]);
}

// ===========================================================================
// Kernel 3: causal flash attention. BR=64 (4 warps), BC=32, double-buffered,
// 128 threads, 2 CTAs/SM.  QK^T bf16x3; PV fp16 single pass.
// ===========================================================================
#define FB_ROWB 272                      // 128 elems * 2B + 16B pad
#define F_QH 0
#define F_QL 17408                       // 64*272
#define F_KV 34816
#define F_KVSTG 26112                    // per stage: Kh,Kl,Vf @ 8704 each
#define F_SMEM_BYTES (F_KV + 2 * F_KVSTG)   // 87,040

__global__ __launch_bounds__(128, 2)
void flash_hmma_kernel()
{
    extern __shared__ char sm[];
    const uint32_t sb = smem_u32(sm);
    const int tid  = threadIdx.x;
    const int w    = tid >> 5;
    const int lane = tid & 31;
    const int i0   = (int)(gridDim.x - 1 - blockIdx.x) * 64;
    const int bh   = blockIdx.y;
    const int b    = bh >> 4;
    const int h    = bh & 15;
    const size_t kvbase = (size_t)bh * TSEQ * HD;

    // ---- prologue: Q (hi+lo) and KV tile 0 ----
    {
        const size_t qgbase = kvbase + (size_t)i0 * HD;
#pragma unroll
        for (int it = 0; it < 16; ++it) {
            const int idx = (it & 7) * 128 + tid;
            const int row = idx >> 4;
            const int ch  = idx & 15;
            const uint32_t dst = sb + ((it < 8) ? F_QH : F_QL) +
                                 row * FB_ROWB + ch * 16;
            const __nv_bfloat16* src = (it < 8) ? g_qh : g_ql;
            CP16(dst, src + qgbase + (size_t)row * HD + ch * 8);
        }
#pragma unroll
        for (int it = 0; it < 12; ++it) {
            const int mat = it >> 2;                  // 0:Kh 1:Kl 2:Vf
            const int idx = (it & 3) * 128 + tid;     // 0..511
            const int row = idx >> 4;
            const int ch  = idx & 15;
            const uint32_t dst = sb + F_KV + mat * 8704 +
                                 row * FB_ROWB + ch * 16;
            const void* src =
                (mat == 0) ? (const void*)(g_kh + kvbase + (size_t)row * HD + ch * 8)
              : (mat == 1) ? (const void*)(g_kl + kvbase + (size_t)row * HD + ch * 8)
                           : (const void*)(g_vf + kvbase + (size_t)row * HD + ch * 8);
            CP16(dst, src);
        }
        CP_COMMIT();
    }

    const int r   = lane & 7;
    const int sel = lane >> 3;
    const uint32_t qBase = (uint32_t)((w * 16 + r + (sel & 1) * 8) * FB_ROWB +
                                      (sel >> 1) * 16);
    const uint32_t kBase = (uint32_t)((r + (sel >> 1) * 8) * FB_ROWB +
                                      (sel & 1) * 16);
    const uint32_t vBase = (uint32_t)(((sel & 1) * 8 + r) * FB_ROWB +
                                      (sel >> 1) * 16);

    float o[16][4];
#pragma unroll
    for (int i = 0; i < 16; i++)
#pragma unroll
        for (int t = 0; t < 4; t++) o[i][t] = 0.f;
    float m1 = -1e30f, m2 = -1e30f, l1 = 0.f, l2 = 0.f;
    const int grow1 = i0 + w * 16 + (lane >> 2);
    const int grow2 = grow1 + 8;

    const int ntiles = (i0 >> 5) + 2;
    for (int jt = 0; jt < ntiles; ++jt) {
        const int j0 = jt * 32;
        if (jt + 1 < ntiles) {
            const int nj0 = j0 + 32;
            const uint32_t stg = sb + F_KV + ((jt + 1) & 1) * F_KVSTG;
#pragma unroll
            for (int it = 0; it < 12; ++it) {
                const int mat = it >> 2;
                const int idx = (it & 3) * 128 + tid;
                const int row = idx >> 4;
                const int ch  = idx & 15;
                const uint32_t dst = stg + mat * 8704 + row * FB_ROWB + ch * 16;
                const void* src =
                    (mat == 0) ? (const void*)(g_kh + kvbase + (size_t)(nj0 + row) * HD + ch * 8)
                  : (mat == 1) ? (const void*)(g_kl + kvbase + (size_t)(nj0 + row) * HD + ch * 8)
                               : (const void*)(g_vf + kvbase + (size_t)(nj0 + row) * HD + ch * 8);
                CP16(dst, src);
            }
            CP_COMMIT();
            CP_WAIT1();
        } else {
            CP_WAIT0();
        }
        __syncthreads();

        const uint32_t stg = sb + F_KV + (jt & 1) * F_KVSTG;
        const uint32_t KH = stg, KL = stg + 8704, VF = stg + 17408;

        // ---- S = Q K^T (bf16x3), per warp 16x32 ----
        float s[4][4];
#pragma unroll
        for (int i = 0; i < 4; i++)
#pragma unroll
            for (int t = 0; t < 4; t++) s[i][t] = 0.f;

#pragma unroll
        for (int kk = 0; kk < 8; ++kk) {
            uint32_t ah[4], al[4];
            ldsm4(sb + F_QH + qBase + kk * 32, ah);
            ldsm4(sb + F_QL + qBase + kk * 32, al);
#pragma unroll
            for (int j = 0; j < 2; ++j) {
                const uint32_t kA = kBase + j * (16 * FB_ROWB) + kk * 32;
                uint32_t bhf[4], blf[4];
                ldsm4(KH + kA, bhf);
                ldsm4(KL + kA, blf);
                mma16816(s[j * 2 + 0], ah, bhf[0], bhf[1]);
                mma16816(s[j * 2 + 1], ah, bhf[2], bhf[3]);
                mma16816(s[j * 2 + 0], ah, blf[0], blf[1]);
                mma16816(s[j * 2 + 1], ah, blf[2], blf[3]);
                mma16816(s[j * 2 + 0], al, bhf[0], bhf[1]);
                mma16816(s[j * 2 + 1], al, bhf[2], bhf[3]);
            }
        }

        // ---- causal mask ----
        if (j0 + 31 > i0 + w * 16) {
#pragma unroll
            for (int t8 = 0; t8 < 4; ++t8) {
                const int gcol = j0 + t8 * 8 + 2 * (lane & 3);
                if (gcol > grow1)     s[t8][0] = -1e30f;
                if (gcol + 1 > grow1) s[t8][1] = -1e30f;
                if (gcol > grow2)     s[t8][2] = -1e30f;
                if (gcol + 1 > grow2) s[t8][3] = -1e30f;
            }
        }

        // ---- online softmax ----
        float nm1 = m1, nm2 = m2;
#pragma unroll
        for (int t8 = 0; t8 < 4; ++t8) {
            nm1 = fmaxf(nm1, fmaxf(s[t8][0], s[t8][1]));
            nm2 = fmaxf(nm2, fmaxf(s[t8][2], s[t8][3]));
        }
        nm1 = fmaxf(nm1, __shfl_xor_sync(0xffffffffu, nm1, 1));
        nm1 = fmaxf(nm1, __shfl_xor_sync(0xffffffffu, nm1, 2));
        nm2 = fmaxf(nm2, __shfl_xor_sync(0xffffffffu, nm2, 1));
        nm2 = fmaxf(nm2, __shfl_xor_sync(0xffffffffu, nm2, 2));
        const float a1 = __expf(m1 - nm1);
        const float a2 = __expf(m2 - nm2);
        float r1 = 0.f, r2 = 0.f;
#pragma unroll
        for (int t8 = 0; t8 < 4; ++t8) {
            s[t8][0] = __expf(s[t8][0] - nm1);
            s[t8][1] = __expf(s[t8][1] - nm1);
            s[t8][2] = __expf(s[t8][2] - nm2);
            s[t8][3] = __expf(s[t8][3] - nm2);
            r1 += s[t8][0] + s[t8][1];
            r2 += s[t8][2] + s[t8][3];
        }
        r1 += __shfl_xor_sync(0xffffffffu, r1, 1);
        r1 += __shfl_xor_sync(0xffffffffu, r1, 2);
        r2 += __shfl_xor_sync(0xffffffffu, r2, 1);
        r2 += __shfl_xor_sync(0xffffffffu, r2, 2);
        l1 = l1 * a1 + r1;
        l2 = l2 * a2 + r2;
        m1 = nm1; m2 = nm2;
#pragma unroll
        for (int i = 0; i < 16; ++i) {
            o[i][0] *= a1; o[i][1] *= a1;
            o[i][2] *= a2; o[i][3] *= a2;
        }

        // ---- O += Ph Vf, fp16, single pass ----
#pragma unroll
        for (int kk = 0; kk < 2; ++kk) {
            uint32_t pah[4];
            {
                const float* p0 = s[2 * kk];
                const float* p1 = s[2 * kk + 1];
                pah[0] = pack2h(p0[0], p0[1]);
                pah[1] = pack2h(p0[2], p0[3]);
                pah[2] = pack2h(p1[0], p1[1]);
                pah[3] = pack2h(p1[2], p1[3]);
            }
#pragma unroll
            for (int dc = 0; dc < 4; ++dc) {
                uint32_t vh[2][4];
#pragma unroll
                for (int u = 0; u < 2; ++u) {
                    const uint32_t vA = vBase + kk * (16 * FB_ROWB) +
                                        (dc * 2 + u) * 32;
                    ldsm4t(VF + vA, vh[u]);
                }
#pragma unroll
                for (int u = 0; u < 2; ++u) {
                    mma16816h(o[(dc * 2 + u) * 2 + 0], pah, vh[u][0], vh[u][1]);
                    mma16816h(o[(dc * 2 + u) * 2 + 1], pah, vh[u][2], vh[u][3]);
                }
            }
        }
        __syncthreads();
    }

    // ---- epilogue: att as fp16 single ----
    const float inv1 = 1.0f / l1;
    const float inv2 = 1.0f / l2;
#pragma unroll
    for (int ot = 0; ot < 16; ++ot) {
        const int cold = ot * 8 + 2 * (lane & 3);
        const size_t i1 = ((size_t)(b * TSEQ + grow1)) * DIM + h * HD + cold;
        const size_t i2 = ((size_t)(b * TSEQ + grow2)) * DIM + h * HD + cold;
        *(uint32_t*)&g_af[i1] = pack2h(o[ot][0] * inv1, o[ot][1] * inv1);
        *(uint32_t*)&g_af[i2] = pack2h(o[ot][2] * inv2, o[ot][3] * inv2);
    }
}

// ---------------------------------------------------------------------------
// Kernel 5: per-row L2 normalization of y (in place on d_out)
// ---------------------------------------------------------------------------
__global__ void norm_kernel(float* __restrict__ y)
{
    const int row = blockIdx.x;
    float4* p = (float4*)(y + (size_t)row * DIM);
    float ss = 0.f;
#pragma unroll
    for (int i = threadIdx.x; i < DIM / 4; i += 256) {
        float4 v = p[i];
        ss += v.x * v.x + v.y * v.y + v.z * v.z + v.w * v.w;
    }
    ss += __shfl_xor_sync(0xffffffffu, ss, 16);
    ss += __shfl_xor_sync(0xffffffffu, ss, 8);
    ss += __shfl_xor_sync(0xffffffffu, ss, 4);
    ss += __shfl_xor_sync(0xffffffffu, ss, 2);
    ss += __shfl_xor_sync(0xffffffffu, ss, 1);
    __shared__ float red[8];
    if ((threadIdx.x & 31) == 0) red[threadIdx.x >> 5] = ss;
    __syncthreads();
    float tot = red[0] + red[1] + red[2] + red[3] +
                red[4] + red[5] + red[6] + red[7];
    const float inv = 1.0f / fmaxf(sqrtf(tot), 1e-12f);
#pragma unroll
    for (int i = threadIdx.x; i < DIM / 4; i += 256) {
        float4 v = p[i];
        v.x *= inv; v.y *= inv; v.z *= inv; v.w *= inv;
        p[i] = v;
    }
}

// ---------------------------------------------------------------------------
// Launch
// ---------------------------------------------------------------------------
extern "C" void kernel_launch(void* const* d_in, const int* in_sizes, int n_in,
                              void* d_out, int out_size)
{
    const float* x   = (const float*)d_in[0];
    const float* Wq  = (const float*)d_in[1];
    const float* Wk  = (const float*)d_in[2];
    const float* Wv  = (const float*)d_in[3];
    const float* Wo  = (const float*)d_in[4];
    const float* sqk = (const float*)d_in[5];
    float* y = (float*)d_out;

    __nv_bfloat16 *xh, *xl, *wqh, *wql, *wkh, *wkl;
    __half *xf, *wvf, *wof, *af;
    cudaGetSymbolAddress((void**)&xh,  g_xh);
    cudaGetSymbolAddress((void**)&xl,  g_xl);
    cudaGetSymbolAddress((void**)&wqh, g_wqh);
    cudaGetSymbolAddress((void**)&wql, g_wql);
    cudaGetSymbolAddress((void**)&wkh, g_wkh);
    cudaGetSymbolAddress((void**)&wkl, g_wkl);
    cudaGetSymbolAddress((void**)&xf,  g_xf);
    cudaGetSymbolAddress((void**)&wvf, g_wvf);
    cudaGetSymbolAddress((void**)&wof, g_wof);
    cudaGetSymbolAddress((void**)&af,  g_af);

    cudaFuncSetAttribute(flash_hmma_kernel,
                         cudaFuncAttributeMaxDynamicSharedMemorySize,
                         F_SMEM_BYTES);
    cudaFuncSetAttribute(proj_kernel,
                         cudaFuncAttributeMaxDynamicSharedMemorySize,
                         G_SMEM_BYTES);
    cudaFuncSetAttribute(out_proj_kernel,
                         cudaFuncAttributeMaxDynamicSharedMemorySize,
                         GF_SMEM_BYTES);

    rope_table_kernel<<<TSEQ, 64>>>();

    const int NX4 = MROWS * DIM / 4;   // largest convert
    convert_all_kernel<<<dim3((NX4 + 255) / 256, 5), 256>>>(x, Wq, Wk, Wv, Wo);

    proj_kernel<<<dim3(DIM / 128, MROWS / 128, 3), 256, G_SMEM_BYTES>>>(
        xh, xl, wqh, wql, wkh, wkl, xf, wvf);
    rope_kernel<<<BATCH * NH * TSEQ / 4, 256>>>(sqk);
    flash_hmma_kernel<<<dim3(TSEQ / 64, BATCH * NH), 128, F_SMEM_BYTES>>>();
    out_proj_kernel<<<dim3(DIM / 128, MROWS / 128), 256, GF_SMEM_BYTES>>>(
        af, wof, y);
    norm_kernel<<<MROWS, 256>>>(y);
}